// round 5
// baseline (speedup 1.0000x reference)
#include <cuda_runtime.h>
#include <math.h>

#define NQ    12
#define DIM   4096
#define BATCH 8
#define SEQ   64
#define BT    (BATCH*SEQ)
#define NCTA  256          // 2 states per CTA: (b,t) and (b+4,t)
#define NTHR  256
#define KREG  16

#define PI_D 3.14159265358979323846

typedef unsigned long long u64;

// QKV features [head*3+proj][bt][12]
__device__ float g_qkv[6*BT*NQ];

// ---------------- packed f32x2 helpers ----------------
__device__ __forceinline__ u64 pk2(float lo, float hi) {
    u64 r; asm("mov.b64 %0,{%1,%2};" : "=l"(r) : "f"(lo), "f"(hi)); return r;
}
__device__ __forceinline__ float2 up2(u64 v) {
    float2 r; asm("mov.b64 {%0,%1},%2;" : "=f"(r.x), "=f"(r.y) : "l"(v)); return r;
}
__device__ __forceinline__ u64 mul2_(u64 a, u64 b) {
    u64 d; asm("mul.rn.f32x2 %0,%1,%2;" : "=l"(d) : "l"(a), "l"(b)); return d;
}
__device__ __forceinline__ u64 fma2_(u64 a, u64 b, u64 c) {
    u64 d; asm("fma.rn.f32x2 %0,%1,%2,%3;" : "=l"(d) : "l"(a), "l"(b), "l"(c)); return d;
}
__device__ __forceinline__ u64 add2_(u64 a, u64 b) {
    u64 d; asm("add.rn.f32x2 %0,%1,%2;" : "=l"(d) : "l"(a), "l"(b)); return d;
}
#define NEGM 0x8000000080000000ULL

// packed complex multiply: (ax,ay) *= (bx,by)
__device__ __forceinline__ void cmulp(u64& ax, u64& ay, u64 bx, u64 by) {
    u64 nx = fma2_(ay ^ NEGM, by, mul2_(ax, bx));
    u64 ny = fma2_(ay, bx, mul2_(ax, by));
    ax = nx; ay = ny;
}

// ---------------- layouts ----------------
// A: amp d = (k<<8) | tid            (local bits = qubits 8..11 -> k bits 0..3)
// B: amp d = (tid&31) | ((k&7)<<5) | ((tid>>5)<<8) | ((k>>3)<<11)
//                                    (local bits = qubits 5,6,7 -> k0..2, qubit 11 -> k3)
__device__ __forceinline__ int addrA(int tid, int k) { return (k<<8) | tid; }
__device__ __forceinline__ int addrB(int tid, int k) {
    return (tid & 31) | ((k & 7) << 5) | ((tid >> 5) << 8) | ((k >> 3) << 11);
}
__device__ __forceinline__ int ladd(int d) {         // CX-ladder gather source
    return ((d ^ (d << 1)) & 0xFFE) | (d & 1);
}

// ---------------- gate primitives (packed, 2 states) ----------------
// gate smem layout per gate: 12 u64 = 4 triples [x, y, -y] in slot order g00,g01,g11,g10
__device__ __forceinline__ void gate_lane_p(u64* X, u64* Y, int tid, int i, const u64* g)
{
    int hi = (tid >> i) & 1;
    const u64* gb = g + hi * 6;        // hi=0: (g00,g01)   hi=1: (g11,g10)
    u64 cax = gb[0], cay = gb[1], cayn = gb[2];
    u64 cbx = gb[3], cby = gb[4], cbyn = gb[5];
    unsigned lm = 1u << i;
    #pragma unroll
    for (int k = 0; k < KREG; k++) {
        float2 xs = up2(X[k]), ys = up2(Y[k]);
        u64 Xo = pk2(__shfl_xor_sync(0xffffffffu, xs.x, lm),
                     __shfl_xor_sync(0xffffffffu, xs.y, lm));
        u64 Yo = pk2(__shfl_xor_sync(0xffffffffu, ys.x, lm),
                     __shfl_xor_sync(0xffffffffu, ys.y, lm));
        u64 nx = mul2_(cax, X[k]); nx = fma2_(cayn, Y[k], nx);
        nx = fma2_(cbx, Xo, nx);   nx = fma2_(cbyn, Yo, nx);
        u64 ny = mul2_(cax, Y[k]); ny = fma2_(cay, X[k], ny);
        ny = fma2_(cbx, Yo, ny);   ny = fma2_(cby, Xo, ny);
        X[k] = nx; Y[k] = ny;
    }
}
__device__ __forceinline__ void gate_local_p(u64* X, u64* Y, int m, const u64* g)
{
    u64 ax0 = g[0], ay0 = g[1],  an0 = g[2];     // g00
    u64 bx0 = g[3], by0 = g[4],  bn0 = g[5];     // g01
    u64 bx1 = g[6], by1 = g[7],  bn1 = g[8];     // g11
    u64 ax1 = g[9], ay1 = g[10], an1 = g[11];    // g10
    #pragma unroll
    for (int k = 0; k < KREG; k++) {
        if (k & m) continue;
        int kk = k | m;
        u64 X0 = X[k], Y0 = Y[k], X1 = X[kk], Y1 = Y[kk];
        u64 nx0 = mul2_(ax0, X0); nx0 = fma2_(an0, Y0, nx0);
        nx0 = fma2_(bx0, X1, nx0); nx0 = fma2_(bn0, Y1, nx0);
        u64 ny0 = mul2_(ax0, Y0); ny0 = fma2_(ay0, X0, ny0);
        ny0 = fma2_(bx0, Y1, ny0); ny0 = fma2_(by0, X1, ny0);
        u64 nx1 = mul2_(ax1, X0); nx1 = fma2_(an1, Y0, nx1);
        nx1 = fma2_(bx1, X1, nx1); nx1 = fma2_(bn1, Y1, nx1);
        u64 ny1 = mul2_(ax1, Y0); ny1 = fma2_(ay1, X0, ny1);
        ny1 = fma2_(bx1, Y1, ny1); ny1 = fma2_(by1, X1, ny1);
        X[k] = nx0; Y[k] = ny0; X[kk] = nx1; Y[kk] = ny1;
    }
}
__device__ __forceinline__ void cx011(u64* X, u64* Y, int tid)
{
    if (tid & 1) {
        #pragma unroll
        for (int k = 0; k < 8; k++) {
            u64 t = X[k]; X[k] = X[k+8]; X[k+8] = t;
            t = Y[k]; Y[k] = Y[k+8]; Y[k+8] = t;
        }
    }
}
__device__ __forceinline__ void czp(u64* X, u64* Y, int tid, unsigned mask, bool layB)
{
    #pragma unroll
    for (int k = 0; k < KREG; k++) {
        unsigned d = (unsigned)(layB ? addrB(tid, k) : addrA(tid, k));
        u64 s = (__popc((d & (d >> 1)) & mask) & 1) ? NEGM : 0ULL;
        X[k] ^= s; Y[k] ^= s;
    }
}
// ---------------- layout roundtrips ----------------
__device__ __forceinline__ void rtAB_p(u64* X, u64* Y, u64* wX, u64* wY, int tid, bool ladder)
{
    __syncthreads();
    #pragma unroll
    for (int k = 0; k < KREG; k++) { int a = addrA(tid, k); wX[a] = X[k]; wY[a] = Y[k]; }
    __syncthreads();
    #pragma unroll
    for (int k = 0; k < KREG; k++) {
        int D = addrB(tid, k);
        int s = ladder ? ladd(D) : D;
        X[k] = wX[s]; Y[k] = wY[s];
    }
}
__device__ __forceinline__ void rtBA_p(u64* X, u64* Y, u64* wX, u64* wY, int tid)
{
    __syncthreads();
    #pragma unroll
    for (int k = 0; k < KREG; k++) { int a = addrB(tid, k); wX[a] = X[k]; wY[a] = Y[k]; }
    __syncthreads();
    #pragma unroll
    for (int k = 0; k < KREG; k++) { int a = addrA(tid, k); X[k] = wX[a]; Y[k] = wY[a]; }
}

// packed warp sum
__device__ __forceinline__ u64 wsum(u64 v)
{
    #pragma unroll
    for (int off = 16; off; off >>= 1) {
        float2 t = up2(v);
        v = add2_(v, pk2(__shfl_xor_sync(0xffffffffu, t.x, off),
                         __shfl_xor_sync(0xffffffffu, t.y, off)));
    }
    return v;
}

// write a gate (4 complex entries) as 12 broadcast u64: slots g00,g01,g11,g10, each [x,y,-y]
__device__ __forceinline__ void write12(u64* p, float2 a, float2 b, float2 c, float2 d)
{
    p[0] = pk2(a.x, a.x);  p[1]  = pk2(a.y, a.y);  p[2]  = pk2(-a.y, -a.y);
    p[3] = pk2(b.x, b.x);  p[4]  = pk2(b.y, b.y);  p[5]  = pk2(-b.y, -b.y);
    p[6] = pk2(c.x, c.x);  p[7]  = pk2(c.y, c.y);  p[8]  = pk2(-c.y, -c.y);
    p[9] = pk2(d.x, d.x);  p[10] = pk2(d.y, d.y);  p[11] = pk2(-d.y, -d.y);
}

extern __shared__ u64 smem_u64[];
// [0,4096)       wX
// [4096,8192)    wY
// [8192,10352)   gates (180*12)
// [10352,14448)  eX snapshot
// [14448,18544)  eY snapshot

__global__ void __launch_bounds__(NTHR) qtf_main(
    const float* __restrict__ seq,
    const float* __restrict__ resp,
    const float* __restrict__ headp)
{
    u64* wX   = smem_u64;
    u64* wY   = smem_u64 + 4096;
    u64* sm_g = smem_u64 + 8192;
    u64* eX   = smem_u64 + 10352;
    u64* eY   = smem_u64 + 14448;

    const int tid = threadIdx.x;
    const int cta = blockIdx.x;
    const int b   = cta >> 6;          // 0..3
    const int t   = cta & 63;
    const int bt0 = b * SEQ + t;
    const int bt1 = (b + 4) * SEQ + t;
    const float x0 = seq[bt0];
    const float x1 = seq[bt1];

    // ---- per-CTA gate setup (distributed across threads) ----
    if (tid < 36) {
        float tt = resp[tid*3+0], pp = resp[tid*3+1], ll = resp[tid*3+2];
        float st_, ct, sl, cl, sp, cp, spl, cpl;
        sincosf(0.5f*tt, &st_, &ct);
        sincosf(ll, &sl, &cl);
        sincosf(pp, &sp, &cp);
        sincosf(pp+ll, &spl, &cpl);
        float2 g00 = make_float2(ct, 0.f);
        float2 g01 = make_float2(-cl*st_, -sl*st_);
        float2 g10 = make_float2( cp*st_,  sp*st_);
        float2 g11 = make_float2(cpl*ct,  spl*ct);
        write12(sm_g + tid*12, g00, g01, g11, g10);
    }
    if (tid >= 64 && tid < 64 + 144) {
        int s  = tid - 64;
        int hp = s / 24, gi = s % 24;
        const float* pars = headp + hp*48;
        float th = pars[gi*2], ph = pars[gi*2+1];
        float sn, cs, sh, ch;
        sincosf(0.5f*th, &sn, &cs);
        sincosf(0.5f*ph, &sh, &ch);
        float2 g00 = make_float2( cs*ch, -cs*sh);
        float2 g01 = make_float2(-sn*ch,  sn*sh);
        float2 g10 = make_float2( sn*ch,  sn*sh);
        float2 g11 = make_float2( cs*ch,  cs*sh);
        write12(sm_g + (36 + s)*12, g00, g01, g11, g10);
    }

    u64 X[KREG], Y[KREG];

    // ======== encode: product state with folded ladder+ring perm (layout A) ========
    {
        u64 Fx = pk2(1.f, 1.f), Fy = 0ULL;
        u64 wvx[6][2], wvy[6][2];   // qubits 0,1,8,9,10,11
        #pragma unroll
        for (int i = 0; i < NQ; i++) {
            float2 v0s[2], v1s[2];
            #pragma unroll
            for (int s = 0; s < 2; s++) {
                float xx = s ? x1 : x0;
                float th = xx * (float)(PI_D * (double)(i + 1) / 12.0);
                float ph = xx * (float)(PI_D / (double)(i + 1));
                float sn, c, sh, ch;
                __sincosf(0.5f*th, &sn, &c);
                __sincosf(0.5f*ph, &sh, &ch);
                float am = (c - sn) * 0.70710678118654752f;
                float ap = (c + sn) * 0.70710678118654752f;
                v0s[s] = make_float2(am*ch, -am*sh);
                v1s[s] = make_float2(ap*ch,  ap*sh);
            }
            u64 v0x = pk2(v0s[0].x, v0s[1].x), v0y = pk2(v0s[0].y, v0s[1].y);
            u64 v1x = pk2(v1s[0].x, v1s[1].x), v1y = pk2(v1s[0].y, v1s[1].y);
            if (i >= 2 && i <= 7) {
                int bit = ((tid >> (i-1)) ^ (tid >> i)) & 1;
                cmulp(Fx, Fy, bit ? v1x : v0x, bit ? v1y : v0y);
            } else {
                int vi = (i < 2) ? i : (i - 6);
                wvx[vi][0] = v0x; wvy[vi][0] = v0y;
                wvx[vi][1] = v1x; wvy[vi][1] = v1y;
            }
        }
        int a0 = tid & 1, a1 = (tid >> 1) & 1, a7 = (tid >> 7) & 1;
        #pragma unroll
        for (int k = 0; k < KREG; k++) {
            int k0 = k & 1, k1 = (k >> 1) & 1, k2 = (k >> 2) & 1, k3 = (k >> 3) & 1;
            u64 ax = Fx, ay = Fy;
            int s0 = a0 ^ k3, s1 = a0 ^ a1 ^ k3, s2 = a7 ^ k0;
            int s3 = k0 ^ k1, s4 = k1 ^ k2, s5 = k2 ^ k3;
            cmulp(ax, ay, s0 ? wvx[0][1] : wvx[0][0], s0 ? wvy[0][1] : wvy[0][0]);
            cmulp(ax, ay, s1 ? wvx[1][1] : wvx[1][0], s1 ? wvy[1][1] : wvy[1][0]);
            cmulp(ax, ay, s2 ? wvx[2][1] : wvx[2][0], s2 ? wvy[2][1] : wvy[2][0]);
            cmulp(ax, ay, s3 ? wvx[3][1] : wvx[3][0], s3 ? wvy[3][1] : wvy[3][0]);
            cmulp(ax, ay, s4 ? wvx[4][1] : wvx[4][0], s4 ? wvy[4][1] : wvy[4][0]);
            cmulp(ax, ay, s5 ? wvx[5][1] : wvx[5][0], s5 ? wvy[5][1] : wvy[5][0]);
            X[k] = ax; Y[k] = ay;
        }
    }
    __syncthreads();   // gate setup writes complete

    // ======== reservoir: 3 layers, alternating layouts ========
    #define RGATE(l,i) (sm_g + ((l)*12 + (i))*12)
    // layer 0 (A -> B)
    {
        #pragma unroll
        for (int i = 0; i < 5; i++) gate_lane_p(X, Y, tid, i, RGATE(0,i));
        gate_local_p(X, Y, 1, RGATE(0,8));  gate_local_p(X, Y, 2, RGATE(0,9));
        gate_local_p(X, Y, 4, RGATE(0,10)); gate_local_p(X, Y, 8, RGATE(0,11));
        rtAB_p(X, Y, wX, wY, tid, false);
        gate_local_p(X, Y, 1, RGATE(0,5));  gate_local_p(X, Y, 2, RGATE(0,6));
        gate_local_p(X, Y, 4, RGATE(0,7));
        czp(X, Y, tid, 0x555u, true); cx011(X, Y, tid);
    }
    // layer 1 (B -> A)
    {
        #pragma unroll
        for (int i = 0; i < 5; i++) gate_lane_p(X, Y, tid, i, RGATE(1,i));
        gate_local_p(X, Y, 1, RGATE(1,5));  gate_local_p(X, Y, 2, RGATE(1,6));
        gate_local_p(X, Y, 4, RGATE(1,7));  gate_local_p(X, Y, 8, RGATE(1,11));
        rtBA_p(X, Y, wX, wY, tid);
        gate_local_p(X, Y, 1, RGATE(1,8));  gate_local_p(X, Y, 2, RGATE(1,9));
        gate_local_p(X, Y, 4, RGATE(1,10));
        czp(X, Y, tid, 0x2AAu, false); cx011(X, Y, tid);
    }
    // layer 2 (A -> B)
    {
        #pragma unroll
        for (int i = 0; i < 5; i++) gate_lane_p(X, Y, tid, i, RGATE(2,i));
        gate_local_p(X, Y, 1, RGATE(2,8));  gate_local_p(X, Y, 2, RGATE(2,9));
        gate_local_p(X, Y, 4, RGATE(2,10)); gate_local_p(X, Y, 8, RGATE(2,11));
        rtAB_p(X, Y, wX, wY, tid, false);
        gate_local_p(X, Y, 1, RGATE(2,5));  gate_local_p(X, Y, 2, RGATE(2,6));
        gate_local_p(X, Y, 4, RGATE(2,7));
        czp(X, Y, tid, 0x555u, true); cx011(X, Y, tid);
    }

    // snapshot encoded state (layout B; own cells only)
    #pragma unroll
    for (int k = 0; k < KREG; k++) { int a = (k<<8)|tid; eX[a] = X[k]; eY[a] = Y[k]; }

    // ======== projections (Q only at t = SEQ-1) ========
    const bool lastt = (t == SEQ - 1);
    bool first = true;
    for (int h = 0; h < 2; h++) {
        for (int p = 0; p < 3; p++) {
            if (p == 0 && !lastt) continue;
            if (!first) {
                #pragma unroll
                for (int k = 0; k < KREG; k++) { int a = (k<<8)|tid; X[k] = eX[a]; Y[k] = eY[a]; }
            }
            first = false;
            const int hp = h*3 + p;
            #define PGATE(l,i) (sm_g + (36 + (hp)*24 + (l)*12 + (i))*12)
            // attn layer 0 (state in B)
            #pragma unroll
            for (int i = 0; i < 5; i++) gate_lane_p(X, Y, tid, i, PGATE(0,i));
            gate_local_p(X, Y, 1, PGATE(0,5));  gate_local_p(X, Y, 2, PGATE(0,6));
            gate_local_p(X, Y, 4, PGATE(0,7));  gate_local_p(X, Y, 8, PGATE(0,11));
            rtBA_p(X, Y, wX, wY, tid);
            gate_local_p(X, Y, 1, PGATE(0,8));  gate_local_p(X, Y, 2, PGATE(0,9));
            gate_local_p(X, Y, 4, PGATE(0,10));
            rtAB_p(X, Y, wX, wY, tid, true);    // ladder folded into gather
            // attn layer 1 (state in B)
            #pragma unroll
            for (int i = 0; i < 5; i++) gate_lane_p(X, Y, tid, i, PGATE(1,i));
            gate_local_p(X, Y, 1, PGATE(1,5));  gate_local_p(X, Y, 2, PGATE(1,6));
            gate_local_p(X, Y, 4, PGATE(1,7));  gate_local_p(X, Y, 8, PGATE(1,11));
            rtBA_p(X, Y, wX, wY, tid);
            gate_local_p(X, Y, 1, PGATE(1,8));  gate_local_p(X, Y, 2, PGATE(1,9));
            gate_local_p(X, Y, 4, PGATE(1,10));

            // ---- features (layout A, final ladder folded into sign masks) ----
            u64 Sp = 0, B0p = 0, B1p = 0, B2p = 0, B3p = 0;
            #pragma unroll
            for (int k = 0; k < KREG; k++) {
                u64 pr = fma2_(Y[k], Y[k], mul2_(X[k], X[k]));
                Sp = add2_(Sp, pr);
                B0p = add2_(B0p, ( k          & 1) ? (pr ^ NEGM) : pr);
                B1p = add2_(B1p, ((k ^ (k>>1))& 1) ? (pr ^ NEGM) : pr);
                B2p = add2_(B2p, (__popc(k & 7)  & 1) ? (pr ^ NEGM) : pr);
                B3p = add2_(B3p, (__popc(k & 15) & 1) ? (pr ^ NEGM) : pr);
            }
            u64 tmask = (__popc(tid) & 1) ? NEGM : 0ULL;
            u64 acc[NQ];
            acc[0] = B3p ^ tmask;
            acc[1] = B2p ^ tmask;
            acc[2] = B1p ^ tmask;
            acc[3] = B0p ^ tmask;
            #pragma unroll
            for (int q = 4; q < NQ; q++) {
                int mt = 0xFF >> (q - 4);
                acc[q] = Sp ^ ((__popc(tid & mt) & 1) ? NEGM : 0ULL);
            }
            #pragma unroll
            for (int q = 0; q < NQ; q++) acc[q] = wsum(acc[q]);

            __syncthreads();   // wX reads from last rt complete before reuse as scratch
            if ((tid & 31) == 0) {
                int w = tid >> 5;
                #pragma unroll
                for (int q = 0; q < NQ; q++) wX[w*NQ + q] = acc[q];
            }
            __syncthreads();
            if (tid < NQ) {
                float lo = 0.f, hi = 0.f;
                #pragma unroll
                for (int w = 0; w < 8; w++) {
                    float2 v = up2(wX[w*NQ + tid]);
                    lo += v.x; hi += v.y;
                }
                g_qkv[(hp*BT + bt0)*NQ + tid] = lo;
                g_qkv[(hp*BT + bt1)*NQ + tid] = hi;
            }
            __syncthreads();
        }
    }
}

// ---------------- attention (last row only, both heads parallel) + MLP ----------------
__global__ void qtf_head(
    const float* __restrict__ W1, const float* __restrict__ b1,
    const float* __restrict__ W2, const float* __restrict__ b2,
    float* __restrict__ out)
{
    const int b   = blockIdx.x;
    const int tid = threadIdx.x;       // 128
    const int h   = tid >> 6;
    const int s   = tid & 63;
    __shared__ float feat[24];
    __shared__ float redm[2][2], reds[2][2];
    __shared__ float hdn[48];
    if (tid < 24) feat[tid] = 0.0f;
    __syncthreads();

    const float* Q = &g_qkv[((h*3 + 0)*BT + b*SEQ + (SEQ-1))*NQ];
    const float* K = &g_qkv[((h*3 + 1)*BT + b*SEQ)*NQ];
    const float* V = &g_qkv[((h*3 + 2)*BT + b*SEQ)*NQ];
    float sc = 0.0f;
    #pragma unroll
    for (int q = 0; q < NQ; q++) sc += Q[q] * K[s*NQ + q];
    sc *= 0.28867513459481287f;   // 1/sqrt(12)
    float m = sc;
    #pragma unroll
    for (int off = 16; off; off >>= 1)
        m = fmaxf(m, __shfl_xor_sync(0xffffffffu, m, off));
    int w = s >> 5;
    if ((s & 31) == 0) redm[h][w] = m;
    __syncthreads();
    m = fmaxf(redm[h][0], redm[h][1]);
    float e = expf(sc - m);
    float sum = e;
    #pragma unroll
    for (int off = 16; off; off >>= 1)
        sum += __shfl_xor_sync(0xffffffffu, sum, off);
    if ((s & 31) == 0) reds[h][w] = sum;
    __syncthreads();
    sum = reds[h][0] + reds[h][1];
    float wgt = e / sum;
    #pragma unroll
    for (int d = 0; d < NQ; d++) {
        float v = wgt * V[s*NQ + d];
        #pragma unroll
        for (int off = 16; off; off >>= 1)
            v += __shfl_xor_sync(0xffffffffu, v, off);
        if ((s & 31) == 0) atomicAdd(&feat[h*NQ + d], v);
    }
    __syncthreads();

    if (tid < 48) {
        float a = b1[tid];
        #pragma unroll
        for (int i = 0; i < 24; i++) a += feat[i] * W1[i*48 + tid];
        hdn[tid] = 0.5f * a * (1.0f + erff(a * 0.7071067811865476f));
    }
    __syncthreads();
    if (tid < 4) {
        float a = b2[tid];
        #pragma unroll
        for (int j = 0; j < 48; j++) a += hdn[j] * W2[j*4 + tid];
        out[b*4 + tid] = a;
    }
}

extern "C" void kernel_launch(void* const* d_in, const int* in_sizes, int n_in,
                              void* d_out, int out_size)
{
    const float* seq   = (const float*)d_in[0];
    const float* resp  = (const float*)d_in[1];
    const float* headp = (const float*)d_in[2];
    const float* W1    = (const float*)d_in[3];
    const float* b1    = (const float*)d_in[4];
    const float* W2    = (const float*)d_in[5];
    const float* b2    = (const float*)d_in[6];
    float* out = (float*)d_out;

    size_t shbytes = 18544ull * sizeof(u64);   // 148,352 B
    cudaFuncSetAttribute(qtf_main, cudaFuncAttributeMaxDynamicSharedMemorySize, (int)shbytes);

    qtf_main<<<NCTA, NTHR, shbytes>>>(seq, resp, headp);
    qtf_head<<<BATCH, 128>>>(W1, b1, W2, b2, out);
}

// round 6
// speedup vs baseline: 1.4851x; 1.4851x over previous
#include <cuda_runtime.h>
#include <math.h>

#define NQ    12
#define DIM   4096
#define BATCH 8
#define SEQ   64
#define BT    (BATCH*SEQ)
#define NTHR  256
#define KREG  16

#define PI_D 3.14159265358979323846

// QKV features [head*3+proj][bt][12]
__device__ float  g_qkv[6*BT*NQ];
__device__ float2 g_ryres[36];        // reservoir RY coeffs (cos(t/2), sin(t/2))
__device__ float2 g_ryproj[144];      // projection RY coeffs
__device__ float2 g_diag[12*128];     // diag tables: pass*128 + (lo:0-63 | hi:64-127)

// ---------------- complex helpers ----------------
__device__ __forceinline__ float2 cmul(float2 a, float2 b) {
    return make_float2(a.x*b.x - a.y*b.y, a.x*b.y + a.y*b.x);
}

// ---------------- setup: RY coeffs + diagonal phase tables ----------------
// diag pass indices: 0..5 reservoir (pre_l = 2l uses lambda, post_l = 2l+1 uses phi)
//                    6..11 projection hp (layer-0 RZ phases); layer-1 RZ dropped (|amp|^2)
__global__ void qtf_setup(const float* __restrict__ resp, const float* __restrict__ headp)
{
    int j = blockIdx.x * blockDim.x + threadIdx.x;
    if (j < 36) {
        float t = resp[j*3];
        g_ryres[j] = make_float2(cosf(0.5f*t), sinf(0.5f*t));
    } else if (j < 180) {
        int s = j - 36, hp = s / 24, gi = s % 24;
        float t = headp[hp*48 + gi*2];
        g_ryproj[s] = make_float2(cosf(0.5f*t), sinf(0.5f*t));
    }
    int e = j - 192;
    if (e >= 0 && e < 12*128) {
        int pass = e >> 7, m = e & 127;
        int is_hi = (m >> 6) & 1, mb = m & 63;
        float ph = 0.f;
        for (int i = 0; i < 6; i++) {
            if ((mb >> i) & 1) {
                int q = i + is_hi*6;
                float f;
                if (pass < 6) {
                    int l = pass >> 1, kind = pass & 1;   // 0 = pre(lambda), 1 = post(phi)
                    f = resp[(l*12 + q)*3 + (kind ? 1 : 2)];
                } else {
                    f = headp[(pass - 6)*48 + q*2 + 1];
                }
                ph += f;
            }
        }
        g_diag[pass*128 + m] = make_float2(cosf(ph), sinf(ph));
    }
}

// ---------------- layouts ----------------
// A: amp d = (k<<8) | tid            (local = qubits 8..11 on k bits 0..3)
// B: amp d = (tid&31) | ((k&7)<<5) | ((tid>>5)<<8) | ((k>>3)<<11)
//                                    (local = qubits 5,6,7 on k0..2, qubit 11 on k3)
__device__ __forceinline__ int addrA(int tid, int k) { return (k<<8) | tid; }
__device__ __forceinline__ int addrB(int tid, int k) {
    return (tid & 31) | ((k & 7) << 5) | ((tid >> 5) << 8) | ((k >> 3) << 11);
}
__device__ __forceinline__ int ladd(int d) {   // CX-ladder gather source
    return ((d ^ (d << 1)) & 0xFFE) | (d & 1);
}

// ---------------- RY gate primitives (real 2x2) ----------------
__device__ __forceinline__ void ry_lane(float2 st[KREG], int tid, int i, float2 cs)
{
    unsigned lm = 1u << i;
    float c = cs.x;
    float s = ((tid >> i) & 1) ? cs.y : -cs.y;
    #pragma unroll
    for (int k = 0; k < KREG; k++) {
        float ox = __shfl_xor_sync(0xffffffffu, st[k].x, lm);
        float oy = __shfl_xor_sync(0xffffffffu, st[k].y, lm);
        st[k].x = fmaf(c, st[k].x, s*ox);
        st[k].y = fmaf(c, st[k].y, s*oy);
    }
}
__device__ __forceinline__ void ry_local(float2 st[KREG], int m, float2 cs)
{
    float c = cs.x, s = cs.y;
    #pragma unroll
    for (int k = 0; k < KREG; k++) {
        if (k & m) continue;
        int kk = k | m;
        float2 a = st[k], b = st[kk];
        st[k].x  = fmaf(c, a.x, -s*b.x);
        st[k].y  = fmaf(c, a.y, -s*b.y);
        st[kk].x = fmaf(s, a.x,  c*b.x);
        st[kk].y = fmaf(s, a.y,  c*b.y);
    }
}

// ---------------- diagonal (all-RZ layer) passes ----------------
__device__ __forceinline__ void diagA(float2 st[KREG], const float2* T, int tid)
{
    float2 L = T[tid & 63];
    int tt = tid >> 6;
    #pragma unroll
    for (int k = 0; k < KREG; k++) {
        float2 u = cmul(L, T[64 + ((k<<2) | tt)]);
        st[k] = cmul(st[k], u);
    }
}
__device__ __forceinline__ void diagB(float2 st[KREG], const float2* T, int tid)
{
    int lo0 = tid & 31, t57 = tid >> 5;
    #pragma unroll
    for (int k = 0; k < KREG; k++) {
        float2 L = T[lo0 | ((k & 1) << 5)];
        float2 H = T[64 + (((k>>1) & 3) | (t57 << 2) | ((k>>3) << 5))];
        st[k] = cmul(st[k], cmul(L, H));
    }
}

// ---------------- CZ / CX ----------------
__device__ __forceinline__ void cx011(float2 st[KREG], int tid)
{
    if (tid & 1) {
        #pragma unroll
        for (int k = 0; k < 8; k++) {
            float2 t = st[k]; st[k] = st[k+8]; st[k+8] = t;
        }
    }
}
__device__ __forceinline__ void czA(float2 st[KREG], int tid, unsigned mask)
{
    #pragma unroll
    for (int k = 0; k < KREG; k++) {
        unsigned d = (unsigned)addrA(tid, k);
        if (__popc((d & (d >> 1)) & mask) & 1) { st[k].x = -st[k].x; st[k].y = -st[k].y; }
    }
}
__device__ __forceinline__ void czB(float2 st[KREG], int tid, unsigned mask)
{
    #pragma unroll
    for (int k = 0; k < KREG; k++) {
        unsigned d = (unsigned)addrB(tid, k);
        if (__popc((d & (d >> 1)) & mask) & 1) { st[k].x = -st[k].x; st[k].y = -st[k].y; }
    }
}

// ---------------- layout roundtrips ----------------
__device__ __forceinline__ void rtAB(float2 st[KREG], float2* work, int tid, bool ladder)
{
    __syncthreads();
    #pragma unroll
    for (int k = 0; k < KREG; k++) work[addrA(tid, k)] = st[k];
    __syncthreads();
    #pragma unroll
    for (int k = 0; k < KREG; k++) {
        int D = addrB(tid, k);
        st[k] = work[ladder ? ladd(D) : D];
    }
}
__device__ __forceinline__ void rtBA(float2 st[KREG], float2* work, int tid)
{
    __syncthreads();
    #pragma unroll
    for (int k = 0; k < KREG; k++) work[addrB(tid, k)] = st[k];
    __syncthreads();
    #pragma unroll
    for (int k = 0; k < KREG; k++) st[k] = work[addrA(tid, k)];
}

extern __shared__ float2 smem[];
// [0,4096) work  [4096,8192) enc snapshot  [8192,8372) RY coeffs  [8372,9908) diag tables

__global__ void __launch_bounds__(NTHR) qtf_main(const float* __restrict__ seq)
{
    float2* work  = smem;
    float2* encs  = smem + 4096;
    float2* sry   = smem + 8192;          // [0,36) res, [36,180) proj
    float2* sdiag = smem + 8372;          // 12*128
    const int tid = threadIdx.x;
    const int bt  = blockIdx.x;
    const int t   = bt & (SEQ - 1);
    const float x = seq[bt];

    for (int j = tid; j < 36;   j += NTHR) sry[j]      = g_ryres[j];
    for (int j = tid; j < 144;  j += NTHR) sry[36+j]   = g_ryproj[j];
    for (int j = tid; j < 1536; j += NTHR) sdiag[j]    = g_diag[j];

    float2 st[KREG];

    // ======== encode: product state with folded ladder+ring perm (layout A) ========
    {
        float2 F = make_float2(1.0f, 0.0f);
        float2 wv[6][2];   // qubits 0,1,8,9,10,11
        #pragma unroll
        for (int i = 0; i < NQ; i++) {
            float th = x * (float)(PI_D * (double)(i + 1) / 12.0);
            float ph = x * (float)(PI_D / (double)(i + 1));
            float s, c, sh, ch;
            __sincosf(0.5f*th, &s, &c);
            __sincosf(0.5f*ph, &sh, &ch);
            float am = (c - s) * 0.70710678118654752f;
            float ap = (c + s) * 0.70710678118654752f;
            float2 v0 = make_float2(am*ch, -am*sh);
            float2 v1 = make_float2(ap*ch,  ap*sh);
            if (i >= 2 && i <= 7) {
                int bit = ((tid >> (i-1)) ^ (tid >> i)) & 1;
                F = cmul(F, bit ? v1 : v0);
            } else {
                int vi = (i < 2) ? i : (i - 6);
                wv[vi][0] = v0; wv[vi][1] = v1;
            }
        }
        int a0 = tid & 1, a1 = (tid >> 1) & 1, a7 = (tid >> 7) & 1;
        #pragma unroll
        for (int k = 0; k < KREG; k++) {
            int k0 = k & 1, k1 = (k >> 1) & 1, k2 = (k >> 2) & 1, k3 = (k >> 3) & 1;
            float2 a = cmul(F, (a0 ^ k3)      ? wv[0][1] : wv[0][0]);
            a = cmul(a, (a0 ^ a1 ^ k3) ? wv[1][1] : wv[1][0]);
            a = cmul(a, (a7 ^ k0)      ? wv[2][1] : wv[2][0]);
            a = cmul(a, (k0 ^ k1)      ? wv[3][1] : wv[3][0]);
            a = cmul(a, (k1 ^ k2)      ? wv[4][1] : wv[4][0]);
            a = cmul(a, (k2 ^ k3)      ? wv[5][1] : wv[5][0]);
            st[k] = a;
        }
    }
    __syncthreads();   // table loads complete

    // ======== reservoir: u3 = RZ(p) RY(t) RZ(l), layerwise diag/RY/diag ========
    // layer 0 (A -> B)
    diagA(st, sdiag + 0*128, tid);                       // pre0 (lambda)
    #pragma unroll
    for (int i = 0; i < 5; i++) ry_lane(st, tid, i, sry[i]);
    ry_local(st, 1, sry[8]);  ry_local(st, 2, sry[9]);
    ry_local(st, 4, sry[10]); ry_local(st, 8, sry[11]);
    rtAB(st, work, tid, false);
    ry_local(st, 1, sry[5]);  ry_local(st, 2, sry[6]); ry_local(st, 4, sry[7]);
    diagB(st, sdiag + 1*128, tid);                       // post0 (phi)
    czB(st, tid, 0x555u); cx011(st, tid);
    // layer 1 (B -> A)
    diagB(st, sdiag + 2*128, tid);                       // pre1
    #pragma unroll
    for (int i = 0; i < 5; i++) ry_lane(st, tid, i, sry[12+i]);
    ry_local(st, 1, sry[12+5]); ry_local(st, 2, sry[12+6]);
    ry_local(st, 4, sry[12+7]); ry_local(st, 8, sry[12+11]);
    rtBA(st, work, tid);
    ry_local(st, 1, sry[12+8]); ry_local(st, 2, sry[12+9]); ry_local(st, 4, sry[12+10]);
    diagA(st, sdiag + 3*128, tid);                       // post1
    czA(st, tid, 0x2AAu); cx011(st, tid);
    // layer 2 (A -> B)
    diagA(st, sdiag + 4*128, tid);                       // pre2
    #pragma unroll
    for (int i = 0; i < 5; i++) ry_lane(st, tid, i, sry[24+i]);
    ry_local(st, 1, sry[24+8]);  ry_local(st, 2, sry[24+9]);
    ry_local(st, 4, sry[24+10]); ry_local(st, 8, sry[24+11]);
    rtAB(st, work, tid, false);
    ry_local(st, 1, sry[24+5]);  ry_local(st, 2, sry[24+6]); ry_local(st, 4, sry[24+7]);
    diagB(st, sdiag + 5*128, tid);                       // post2
    czB(st, tid, 0x555u); cx011(st, tid);

    // snapshot encoded state (layout B; own cells only)
    #pragma unroll
    for (int k = 0; k < KREG; k++) encs[(k<<8) | tid] = st[k];

    // ======== projections (Q only at t = SEQ-1) ========
    __shared__ float red[NQ];
    const bool lastt = (t == SEQ - 1);
    bool first = true;
    for (int h = 0; h < 2; h++) {
        for (int p = 0; p < 3; p++) {
            if (p == 0 && !lastt) continue;
            if (!first) {
                #pragma unroll
                for (int k = 0; k < KREG; k++) st[k] = encs[(k<<8) | tid];
            }
            first = false;
            const int hp = h*3 + p;
            const float2* gp = sry + 36 + hp*24;
            // attn layer 0 (state in B): RY stage, then RZ diag, then ladder
            #pragma unroll
            for (int i = 0; i < 5; i++) ry_lane(st, tid, i, gp[i]);
            ry_local(st, 1, gp[5]); ry_local(st, 2, gp[6]);
            ry_local(st, 4, gp[7]); ry_local(st, 8, gp[11]);
            rtBA(st, work, tid);
            ry_local(st, 1, gp[8]); ry_local(st, 2, gp[9]); ry_local(st, 4, gp[10]);
            diagA(st, sdiag + (6 + hp)*128, tid);        // layer-0 RZ phases
            rtAB(st, work, tid, true);                   // ladder folded into gather
            // attn layer 1 (state in B): RY stage only (final RZ diag dropped: |amp|^2)
            #pragma unroll
            for (int i = 0; i < 5; i++) ry_lane(st, tid, i, gp[12+i]);
            ry_local(st, 1, gp[12+5]); ry_local(st, 2, gp[12+6]);
            ry_local(st, 4, gp[12+7]); ry_local(st, 8, gp[12+11]);
            rtBA(st, work, tid);
            ry_local(st, 1, gp[12+8]); ry_local(st, 2, gp[12+9]); ry_local(st, 4, gp[12+10]);

            // ---- features (layout A, final ladder folded into sign masks) ----
            float S = 0.f, B0 = 0.f, B1 = 0.f, B2 = 0.f, B3 = 0.f;
            #pragma unroll
            for (int k = 0; k < KREG; k++) {
                float pr = st[k].x*st[k].x + st[k].y*st[k].y;
                S += pr;
                B0 += ( k          & 1) ? -pr : pr;
                B1 += ((k ^ (k>>1))& 1) ? -pr : pr;
                B2 += (__popc(k & 7)  & 1) ? -pr : pr;
                B3 += (__popc(k & 15) & 1) ? -pr : pr;
            }
            float tsgn = (__popc(tid) & 1) ? -1.f : 1.f;
            float acc[NQ];
            acc[0] = tsgn * B3;
            acc[1] = tsgn * B2;
            acc[2] = tsgn * B1;
            acc[3] = tsgn * B0;
            #pragma unroll
            for (int q = 4; q < NQ; q++) {
                int mt = 0xFF >> (q - 4);
                acc[q] = (__popc(tid & mt) & 1) ? -S : S;
            }
            #pragma unroll
            for (int q = 0; q < NQ; q++) {
                float v = acc[q];
                #pragma unroll
                for (int o = 16; o; o >>= 1)
                    v += __shfl_xor_sync(0xffffffffu, v, o);
                acc[q] = v;
            }
            if (tid < NQ) red[tid] = 0.f;
            __syncthreads();
            if ((tid & 31) == 0) {
                #pragma unroll
                for (int q = 0; q < NQ; q++) atomicAdd(&red[q], acc[q]);
            }
            __syncthreads();
            if (tid < NQ)
                g_qkv[(hp*BT + bt)*NQ + tid] = red[tid];
            __syncthreads();
        }
    }
}

// ---------------- attention (last row only, both heads parallel) + MLP ----------------
__global__ void qtf_head(
    const float* __restrict__ W1, const float* __restrict__ b1,
    const float* __restrict__ W2, const float* __restrict__ b2,
    float* __restrict__ out)
{
    const int b   = blockIdx.x;
    const int tid = threadIdx.x;       // 128
    const int h   = tid >> 6;
    const int s   = tid & 63;
    __shared__ float feat[24];
    __shared__ float redm[2][2], reds[2][2];
    __shared__ float hdn[48];
    if (tid < 24) feat[tid] = 0.0f;
    __syncthreads();

    const float* Q = &g_qkv[((h*3 + 0)*BT + b*SEQ + (SEQ-1))*NQ];
    const float* K = &g_qkv[((h*3 + 1)*BT + b*SEQ)*NQ];
    const float* V = &g_qkv[((h*3 + 2)*BT + b*SEQ)*NQ];
    float sc = 0.0f;
    #pragma unroll
    for (int q = 0; q < NQ; q++) sc += Q[q] * K[s*NQ + q];
    sc *= 0.28867513459481287f;   // 1/sqrt(12)
    float m = sc;
    #pragma unroll
    for (int off = 16; off; off >>= 1)
        m = fmaxf(m, __shfl_xor_sync(0xffffffffu, m, off));
    int w = s >> 5;
    if ((s & 31) == 0) redm[h][w] = m;
    __syncthreads();
    m = fmaxf(redm[h][0], redm[h][1]);
    float e = expf(sc - m);
    float sum = e;
    #pragma unroll
    for (int off = 16; off; off >>= 1)
        sum += __shfl_xor_sync(0xffffffffu, sum, off);
    if ((s & 31) == 0) reds[h][w] = sum;
    __syncthreads();
    sum = reds[h][0] + reds[h][1];
    float wgt = e / sum;
    #pragma unroll
    for (int d = 0; d < NQ; d++) {
        float v = wgt * V[s*NQ + d];
        #pragma unroll
        for (int off = 16; off; off >>= 1)
            v += __shfl_xor_sync(0xffffffffu, v, off);
        if ((s & 31) == 0) atomicAdd(&feat[h*NQ + d], v);
    }
    __syncthreads();

    if (tid < 48) {
        float a = b1[tid];
        #pragma unroll
        for (int i = 0; i < 24; i++) a += feat[i] * W1[i*48 + tid];
        hdn[tid] = 0.5f * a * (1.0f + erff(a * 0.7071067811865476f));
    }
    __syncthreads();
    if (tid < 4) {
        float a = b2[tid];
        #pragma unroll
        for (int j = 0; j < 48; j++) a += hdn[j] * W2[j*4 + tid];
        out[b*4 + tid] = a;
    }
}

extern "C" void kernel_launch(void* const* d_in, const int* in_sizes, int n_in,
                              void* d_out, int out_size)
{
    const float* seq   = (const float*)d_in[0];
    const float* resp  = (const float*)d_in[1];
    const float* headp = (const float*)d_in[2];
    const float* W1    = (const float*)d_in[3];
    const float* b1    = (const float*)d_in[4];
    const float* W2    = (const float*)d_in[5];
    const float* b2    = (const float*)d_in[6];
    float* out = (float*)d_out;

    size_t shbytes = 9908ull * sizeof(float2);   // 79,264 B
    cudaFuncSetAttribute(qtf_main, cudaFuncAttributeMaxDynamicSharedMemorySize, (int)shbytes);

    qtf_setup<<<8, 256>>>(resp, headp);
    qtf_main<<<BT, NTHR, shbytes>>>(seq);
    qtf_head<<<BATCH, 128>>>(W1, b1, W2, b2, out);
}

// round 7
// speedup vs baseline: 1.5624x; 1.0520x over previous
#include <cuda_runtime.h>
#include <math.h>

#define NQ    12
#define DIM   4096
#define BATCH 8
#define SEQ   64
#define BT    (BATCH*SEQ)
#define NTHR  256
#define KREG  16

#define PI_D 3.14159265358979323846

typedef unsigned long long u64;

// QKV features [head*3+proj][bt][12]
__device__ float  g_qkv[6*BT*NQ];
__device__ float2 g_ryres[36];        // reservoir RY coeffs (cos(t/2), sin(t/2))
__device__ float2 g_ryproj[144];      // projection RY coeffs
__device__ float2 g_diag[12*128];     // diag tables: pass*128 + (lo:0-63 | hi:64-127)

// ---------------- packed f32x2 helpers ----------------
__device__ __forceinline__ u64 pk2(float lo, float hi) {
    u64 r; asm("mov.b64 %0,{%1,%2};" : "=l"(r) : "f"(lo), "f"(hi)); return r;
}
__device__ __forceinline__ float2 up2(u64 v) {
    float2 r; asm("mov.b64 {%0,%1},%2;" : "=f"(r.x), "=f"(r.y) : "l"(v)); return r;
}
__device__ __forceinline__ u64 mul2_(u64 a, u64 b) {
    u64 d; asm("mul.rn.f32x2 %0,%1,%2;" : "=l"(d) : "l"(a), "l"(b)); return d;
}
__device__ __forceinline__ u64 fma2_(u64 a, u64 b, u64 c) {
    u64 d; asm("fma.rn.f32x2 %0,%1,%2,%3;" : "=l"(d) : "l"(a), "l"(b), "l"(c)); return d;
}

// ---------------- complex helpers ----------------
__device__ __forceinline__ float2 cmul(float2 a, float2 b) {
    return make_float2(a.x*b.x - a.y*b.y, a.x*b.y + a.y*b.x);
}

// ---------------- setup: RY coeffs + diag tables (CZ folded in) ----------------
// diag passes: 0..5 reservoir (pre_l=2l lambda, post_l=2l+1 phi [+CZ folded]),
//              6..11 projection layer-0 RZ; final projection RZ dropped (|amp|^2)
__global__ void qtf_setup(const float* __restrict__ resp, const float* __restrict__ headp)
{
    int j = blockIdx.x * blockDim.x + threadIdx.x;
    if (j < 36) {
        float t = resp[j*3];
        g_ryres[j] = make_float2(cosf(0.5f*t), sinf(0.5f*t));
    } else if (j < 180) {
        int s = j - 36, hp = s / 24, gi = s % 24;
        float t = headp[hp*48 + gi*2];
        g_ryproj[s] = make_float2(cosf(0.5f*t), sinf(0.5f*t));
    }
    int e = j - 192;
    if (e >= 0 && e < 12*128) {
        int pass = e >> 7, m = e & 127;
        int is_hi = (m >> 6) & 1, mb = m & 63;
        float ph = 0.f;
        for (int i = 0; i < 6; i++) {
            if ((mb >> i) & 1) {
                int q = i + is_hi*6;
                float f;
                if (pass < 6) {
                    int l = pass >> 1, kind = pass & 1;   // 0 = pre(lambda), 1 = post(phi)
                    f = resp[(l*12 + q)*3 + (kind ? 1 : 2)];
                } else {
                    f = headp[(pass - 6)*48 + q*2 + 1];
                }
                ph += f;
            }
        }
        float2 v = make_float2(cosf(ph), sinf(ph));
        // fold CZ signs (both lo and hi halves use same in-half pair masks)
        int neg = 0;
        if (pass == 1 || pass == 5)       // CZ mask 0x555: pairs (0,1),(2,3),(4,5) per half
            neg = __popc(mb & (mb >> 1) & 0x15) & 1;
        else if (pass == 3)               // CZ mask 0x2AA: pairs (1,2),(3,4)/(7,8),(9,10)
            neg = __popc(mb & (mb >> 1) & 0x0A) & 1;
        if (neg) { v.x = -v.x; v.y = -v.y; }
        g_diag[pass*128 + m] = v;
    }
}

// ---------------- layouts ----------------
// A: amp d = (k<<8) | tid            (local = qubits 8..11 on k bits 0..3)
// B: amp d = (tid&31) | ((k&7)<<5) | ((tid>>5)<<8) | ((k>>3)<<11)
__device__ __forceinline__ int addrA(int tid, int k) { return (k<<8) | tid; }
__device__ __forceinline__ int addrB(int tid, int k) {
    return (tid & 31) | ((k & 7) << 5) | ((tid >> 5) << 8) | ((k >> 3) << 11);
}
__device__ __forceinline__ int ladd(int d) {   // CX-ladder gather source
    return ((d ^ (d << 1)) & 0xFFE) | (d & 1);
}

// ---------------- packed RY gate primitives ----------------
__device__ __forceinline__ void ry_lane(float2 st[KREG], int tid, int i, float2 cs)
{
    unsigned lm = 1u << i;
    float s = ((tid >> i) & 1) ? cs.y : -cs.y;
    u64 c2 = pk2(cs.x, cs.x), s2 = pk2(s, s);
    #pragma unroll
    for (int k = 0; k < KREG; k++) {
        float ox = __shfl_xor_sync(0xffffffffu, st[k].x, lm);
        float oy = __shfl_xor_sync(0xffffffffu, st[k].y, lm);
        u64 n = fma2_(c2, pk2(st[k].x, st[k].y), mul2_(s2, pk2(ox, oy)));
        st[k] = up2(n);
    }
}
__device__ __forceinline__ void ry_local(float2 st[KREG], int m, float2 cs)
{
    u64 c2 = pk2(cs.x, cs.x), s2 = pk2(cs.y, cs.y), ns2 = pk2(-cs.y, -cs.y);
    #pragma unroll
    for (int k = 0; k < KREG; k++) {
        if (k & m) continue;
        int kk = k | m;
        u64 a = pk2(st[k].x, st[k].y), b = pk2(st[kk].x, st[kk].y);
        u64 n0 = fma2_(c2, a, mul2_(ns2, b));
        u64 n1 = fma2_(s2, a, mul2_(c2, b));
        st[k] = up2(n0); st[kk] = up2(n1);
    }
}

// ---------------- diagonal passes (tables via L2) ----------------
__device__ __forceinline__ void diagA(float2 st[KREG], const float2* T, int tid)
{
    float2 L = __ldg(&T[tid & 63]);
    int tt = tid >> 6;
    #pragma unroll
    for (int k = 0; k < KREG; k++) {
        float2 u = cmul(L, __ldg(&T[64 + ((k<<2) | tt)]));
        st[k] = cmul(st[k], u);
    }
}
__device__ __forceinline__ void diagB(float2 st[KREG], const float2* T, int tid)
{
    int lo0 = tid & 31, t57 = tid >> 5;
    #pragma unroll
    for (int k = 0; k < KREG; k++) {
        float2 L = __ldg(&T[lo0 | ((k & 1) << 5)]);
        float2 H = __ldg(&T[64 + (((k>>1) & 3) | (t57 << 2) | ((k>>3) << 5))]);
        st[k] = cmul(st[k], cmul(L, H));
    }
}

// ---------------- CX(0,11): local in both layouts ----------------
__device__ __forceinline__ void cx011(float2 st[KREG], int tid)
{
    if (tid & 1) {
        #pragma unroll
        for (int k = 0; k < 8; k++) {
            float2 t = st[k]; st[k] = st[k+8]; st[k+8] = t;
        }
    }
}

// ---------------- layout roundtrips ----------------
__device__ __forceinline__ void rtAB(float2 st[KREG], float2* work, int tid, bool ladder)
{
    __syncthreads();
    #pragma unroll
    for (int k = 0; k < KREG; k++) work[addrA(tid, k)] = st[k];
    __syncthreads();
    #pragma unroll
    for (int k = 0; k < KREG; k++) {
        int D = addrB(tid, k);
        st[k] = work[ladder ? ladd(D) : D];
    }
}
__device__ __forceinline__ void rtBA(float2 st[KREG], float2* work, int tid)
{
    __syncthreads();
    #pragma unroll
    for (int k = 0; k < KREG; k++) work[addrB(tid, k)] = st[k];
    __syncthreads();
    #pragma unroll
    for (int k = 0; k < KREG; k++) st[k] = work[addrA(tid, k)];
}

extern __shared__ float2 smem[];
// [0,4096) work   [4096,8192) enc snapshot   [8192,8372) RY coeffs

__global__ void __launch_bounds__(NTHR, 3) qtf_main(const float* __restrict__ seq)
{
    float2* work = smem;
    float2* encs = smem + 4096;
    float2* sry  = smem + 8192;           // [0,36) res, [36,180) proj
    const int tid = threadIdx.x;
    const int bt  = blockIdx.x;
    const int t   = bt & (SEQ - 1);
    const float x = seq[bt];

    for (int j = tid; j < 36;  j += NTHR) sry[j]    = g_ryres[j];
    for (int j = tid; j < 144; j += NTHR) sry[36+j] = g_ryproj[j];

    float2 st[KREG];

    // ======== encode: product state with folded ladder+ring perm (layout A) ========
    {
        float2 F = make_float2(1.0f, 0.0f);
        float2 wv[6][2];   // qubits 0,1,8,9,10,11
        #pragma unroll
        for (int i = 0; i < NQ; i++) {
            float th = x * (float)(PI_D * (double)(i + 1) / 12.0);
            float ph = x * (float)(PI_D / (double)(i + 1));
            float s, c, sh, ch;
            __sincosf(0.5f*th, &s, &c);
            __sincosf(0.5f*ph, &sh, &ch);
            float am = (c - s) * 0.70710678118654752f;
            float ap = (c + s) * 0.70710678118654752f;
            float2 v0 = make_float2(am*ch, -am*sh);
            float2 v1 = make_float2(ap*ch,  ap*sh);
            if (i >= 2 && i <= 7) {
                int bit = ((tid >> (i-1)) ^ (tid >> i)) & 1;
                F = cmul(F, bit ? v1 : v0);
            } else {
                int vi = (i < 2) ? i : (i - 6);
                wv[vi][0] = v0; wv[vi][1] = v1;
            }
        }
        int a0 = tid & 1, a1 = (tid >> 1) & 1, a7 = (tid >> 7) & 1;
        #pragma unroll
        for (int k = 0; k < KREG; k++) {
            int k0 = k & 1, k1 = (k >> 1) & 1, k2 = (k >> 2) & 1, k3 = (k >> 3) & 1;
            float2 a = cmul(F, (a0 ^ k3)      ? wv[0][1] : wv[0][0]);
            a = cmul(a, (a0 ^ a1 ^ k3) ? wv[1][1] : wv[1][0]);
            a = cmul(a, (a7 ^ k0)      ? wv[2][1] : wv[2][0]);
            a = cmul(a, (k0 ^ k1)      ? wv[3][1] : wv[3][0]);
            a = cmul(a, (k1 ^ k2)      ? wv[4][1] : wv[4][0]);
            a = cmul(a, (k2 ^ k3)      ? wv[5][1] : wv[5][0]);
            st[k] = a;
        }
    }
    __syncthreads();   // coeff loads complete

    // ======== reservoir: diag(pre) / RY / diag(post+CZ) / CX ========
    // layer 0 (A -> B)
    diagA(st, g_diag + 0*128, tid);
    #pragma unroll
    for (int i = 0; i < 5; i++) ry_lane(st, tid, i, sry[i]);
    ry_local(st, 1, sry[8]);  ry_local(st, 2, sry[9]);
    ry_local(st, 4, sry[10]); ry_local(st, 8, sry[11]);
    rtAB(st, work, tid, false);
    ry_local(st, 1, sry[5]);  ry_local(st, 2, sry[6]); ry_local(st, 4, sry[7]);
    diagB(st, g_diag + 1*128, tid);         // post0 + CZ(0x555) folded
    cx011(st, tid);
    // layer 1 (B -> A)
    diagB(st, g_diag + 2*128, tid);
    #pragma unroll
    for (int i = 0; i < 5; i++) ry_lane(st, tid, i, sry[12+i]);
    ry_local(st, 1, sry[12+5]); ry_local(st, 2, sry[12+6]);
    ry_local(st, 4, sry[12+7]); ry_local(st, 8, sry[12+11]);
    rtBA(st, work, tid);
    ry_local(st, 1, sry[12+8]); ry_local(st, 2, sry[12+9]); ry_local(st, 4, sry[12+10]);
    diagA(st, g_diag + 3*128, tid);         // post1 + CZ(0x2AA) separable part folded
    if (((tid >> 5) & (tid >> 6)) & 1) {    // CZ(0x2AA) straddle pair (5,6): bits in tid
        #pragma unroll
        for (int k = 0; k < KREG; k++) { st[k].x = -st[k].x; st[k].y = -st[k].y; }
    }
    cx011(st, tid);
    // layer 2 (A -> B)
    diagA(st, g_diag + 4*128, tid);
    #pragma unroll
    for (int i = 0; i < 5; i++) ry_lane(st, tid, i, sry[24+i]);
    ry_local(st, 1, sry[24+8]);  ry_local(st, 2, sry[24+9]);
    ry_local(st, 4, sry[24+10]); ry_local(st, 8, sry[24+11]);
    rtAB(st, work, tid, false);
    ry_local(st, 1, sry[24+5]);  ry_local(st, 2, sry[24+6]); ry_local(st, 4, sry[24+7]);
    diagB(st, g_diag + 5*128, tid);         // post2 + CZ(0x555) folded
    cx011(st, tid);

    // snapshot encoded state (layout B; own cells only)
    #pragma unroll
    for (int k = 0; k < KREG; k++) encs[(k<<8) | tid] = st[k];

    // ======== projections (Q only at t = SEQ-1) ========
    __shared__ float red[NQ];
    const bool lastt = (t == SEQ - 1);
    bool first = true;
    for (int h = 0; h < 2; h++) {
        for (int p = 0; p < 3; p++) {
            if (p == 0 && !lastt) continue;
            if (!first) {
                #pragma unroll
                for (int k = 0; k < KREG; k++) st[k] = encs[(k<<8) | tid];
            }
            first = false;
            const int hp = h*3 + p;
            const float2* gp = sry + 36 + hp*24;
            // attn layer 0 (state in B)
            #pragma unroll
            for (int i = 0; i < 5; i++) ry_lane(st, tid, i, gp[i]);
            ry_local(st, 1, gp[5]); ry_local(st, 2, gp[6]);
            ry_local(st, 4, gp[7]); ry_local(st, 8, gp[11]);
            rtBA(st, work, tid);
            ry_local(st, 1, gp[8]); ry_local(st, 2, gp[9]); ry_local(st, 4, gp[10]);
            diagA(st, g_diag + (6 + hp)*128, tid);   // layer-0 RZ phases
            rtAB(st, work, tid, true);               // ladder folded into gather
            // attn layer 1 (state in B): final RZ diag dropped (|amp|^2)
            #pragma unroll
            for (int i = 0; i < 5; i++) ry_lane(st, tid, i, gp[12+i]);
            ry_local(st, 1, gp[12+5]); ry_local(st, 2, gp[12+6]);
            ry_local(st, 4, gp[12+7]); ry_local(st, 8, gp[12+11]);
            rtBA(st, work, tid);
            ry_local(st, 1, gp[12+8]); ry_local(st, 2, gp[12+9]); ry_local(st, 4, gp[12+10]);

            // ---- features (layout A, final ladder folded into sign masks) ----
            float S = 0.f, B0 = 0.f, B1 = 0.f, B2 = 0.f, B3 = 0.f;
            #pragma unroll
            for (int k = 0; k < KREG; k++) {
                float pr = st[k].x*st[k].x + st[k].y*st[k].y;
                S += pr;
                B0 += ( k          & 1) ? -pr : pr;
                B1 += ((k ^ (k>>1))& 1) ? -pr : pr;
                B2 += (__popc(k & 7)  & 1) ? -pr : pr;
                B3 += (__popc(k & 15) & 1) ? -pr : pr;
            }
            float tsgn = (__popc(tid) & 1) ? -1.f : 1.f;
            float acc[NQ];
            acc[0] = tsgn * B3;
            acc[1] = tsgn * B2;
            acc[2] = tsgn * B1;
            acc[3] = tsgn * B0;
            #pragma unroll
            for (int q = 4; q < NQ; q++) {
                int mt = 0xFF >> (q - 4);
                acc[q] = (__popc(tid & mt) & 1) ? -S : S;
            }
            #pragma unroll
            for (int q = 0; q < NQ; q++) {
                float v = acc[q];
                #pragma unroll
                for (int o = 16; o; o >>= 1)
                    v += __shfl_xor_sync(0xffffffffu, v, o);
                acc[q] = v;
            }
            if (tid < NQ) red[tid] = 0.f;
            __syncthreads();
            if ((tid & 31) == 0) {
                #pragma unroll
                for (int q = 0; q < NQ; q++) atomicAdd(&red[q], acc[q]);
            }
            __syncthreads();
            if (tid < NQ)
                g_qkv[(hp*BT + bt)*NQ + tid] = red[tid];
            __syncthreads();
        }
    }
}

// ---------------- attention (last row only, both heads parallel) + MLP ----------------
__global__ void qtf_head(
    const float* __restrict__ W1, const float* __restrict__ b1,
    const float* __restrict__ W2, const float* __restrict__ b2,
    float* __restrict__ out)
{
    const int b   = blockIdx.x;
    const int tid = threadIdx.x;       // 128
    const int h   = tid >> 6;
    const int s   = tid & 63;
    __shared__ float feat[24];
    __shared__ float redm[2][2], reds[2][2];
    __shared__ float hdn[48];
    if (tid < 24) feat[tid] = 0.0f;
    __syncthreads();

    const float* Q = &g_qkv[((h*3 + 0)*BT + b*SEQ + (SEQ-1))*NQ];
    const float* K = &g_qkv[((h*3 + 1)*BT + b*SEQ)*NQ];
    const float* V = &g_qkv[((h*3 + 2)*BT + b*SEQ)*NQ];
    float sc = 0.0f;
    #pragma unroll
    for (int q = 0; q < NQ; q++) sc += Q[q] * K[s*NQ + q];
    sc *= 0.28867513459481287f;   // 1/sqrt(12)
    float m = sc;
    #pragma unroll
    for (int off = 16; off; off >>= 1)
        m = fmaxf(m, __shfl_xor_sync(0xffffffffu, m, off));
    int w = s >> 5;
    if ((s & 31) == 0) redm[h][w] = m;
    __syncthreads();
    m = fmaxf(redm[h][0], redm[h][1]);
    float e = expf(sc - m);
    float sum = e;
    #pragma unroll
    for (int off = 16; off; off >>= 1)
        sum += __shfl_xor_sync(0xffffffffu, sum, off);
    if ((s & 31) == 0) reds[h][w] = sum;
    __syncthreads();
    sum = reds[h][0] + reds[h][1];
    float wgt = e / sum;
    #pragma unroll
    for (int d = 0; d < NQ; d++) {
        float v = wgt * V[s*NQ + d];
        #pragma unroll
        for (int off = 16; off; off >>= 1)
            v += __shfl_xor_sync(0xffffffffu, v, off);
        if ((s & 31) == 0) atomicAdd(&feat[h*NQ + d], v);
    }
    __syncthreads();

    if (tid < 48) {
        float a = b1[tid];
        #pragma unroll
        for (int i = 0; i < 24; i++) a += feat[i] * W1[i*48 + tid];
        hdn[tid] = 0.5f * a * (1.0f + erff(a * 0.7071067811865476f));
    }
    __syncthreads();
    if (tid < 4) {
        float a = b2[tid];
        #pragma unroll
        for (int j = 0; j < 48; j++) a += hdn[j] * W2[j*4 + tid];
        out[b*4 + tid] = a;
    }
}

extern "C" void kernel_launch(void* const* d_in, const int* in_sizes, int n_in,
                              void* d_out, int out_size)
{
    const float* seq   = (const float*)d_in[0];
    const float* resp  = (const float*)d_in[1];
    const float* headp = (const float*)d_in[2];
    const float* W1    = (const float*)d_in[3];
    const float* b1    = (const float*)d_in[4];
    const float* W2    = (const float*)d_in[5];
    const float* b2    = (const float*)d_in[6];
    float* out = (float*)d_out;

    size_t shbytes = 8372ull * sizeof(float2);   // 66,976 B -> occupancy 3
    cudaFuncSetAttribute(qtf_main, cudaFuncAttributeMaxDynamicSharedMemorySize, (int)shbytes);

    qtf_setup<<<8, 256>>>(resp, headp);
    qtf_main<<<BT, NTHR, shbytes>>>(seq);
    qtf_head<<<BATCH, 128>>>(W1, b1, W2, b2, out);
}

// round 8
// speedup vs baseline: 1.6781x; 1.0741x over previous
#include <cuda_runtime.h>
#include <math.h>

#define NQ    12
#define DIM   4096
#define BATCH 8
#define SEQ   64
#define BT    (BATCH*SEQ)
#define NTHR  256
#define KREG  16

#define PI_D 3.14159265358979323846

typedef unsigned long long u64;

// QKV features [head*3+proj][bt][12]
__device__ float  g_qkv[6*BT*NQ];
__device__ float2 g_ryres[36];        // reservoir RY coeffs (cos(t/2), sin(t/2))
__device__ float2 g_ryproj[144];      // projection RY coeffs
__device__ float2 g_diag[12*128];     // diag tables: pass*128 + (lo:0-63 | hi:64-127)

// ---------------- packed f32x2 helpers ----------------
__device__ __forceinline__ u64 pk2(float lo, float hi) {
    u64 r; asm("mov.b64 %0,{%1,%2};" : "=l"(r) : "f"(lo), "f"(hi)); return r;
}
__device__ __forceinline__ float2 up2(u64 v) {
    float2 r; asm("mov.b64 {%0,%1},%2;" : "=f"(r.x), "=f"(r.y) : "l"(v)); return r;
}
__device__ __forceinline__ u64 mul2_(u64 a, u64 b) {
    u64 d; asm("mul.rn.f32x2 %0,%1,%2;" : "=l"(d) : "l"(a), "l"(b)); return d;
}
__device__ __forceinline__ u64 fma2_(u64 a, u64 b, u64 c) {
    u64 d; asm("fma.rn.f32x2 %0,%1,%2,%3;" : "=l"(d) : "l"(a), "l"(b), "l"(c)); return d;
}
#define NEGM 0x8000000080000000ULL

// ---------------- complex helpers ----------------
__device__ __forceinline__ float2 cmul(float2 a, float2 b) {
    return make_float2(a.x*b.x - a.y*b.y, a.x*b.y + a.y*b.x);
}

// ---------------- setup: RY coeffs + diag tables (CZ folded in) ----------------
// diag passes: 0..5 reservoir (pre_l=2l lambda, post_l=2l+1 phi [+CZ folded]),
//              6..11 projection layer-0 RZ; final projection RZ dropped (|amp|^2)
__global__ void qtf_setup(const float* __restrict__ resp, const float* __restrict__ headp)
{
    int j = blockIdx.x * blockDim.x + threadIdx.x;
    if (j < 36) {
        float t = resp[j*3];
        g_ryres[j] = make_float2(cosf(0.5f*t), sinf(0.5f*t));
    } else if (j < 180) {
        int s = j - 36, hp = s / 24, gi = s % 24;
        float t = headp[hp*48 + gi*2];
        g_ryproj[s] = make_float2(cosf(0.5f*t), sinf(0.5f*t));
    }
    int e = j - 192;
    if (e >= 0 && e < 12*128) {
        int pass = e >> 7, m = e & 127;
        int is_hi = (m >> 6) & 1, mb = m & 63;
        float ph = 0.f;
        for (int i = 0; i < 6; i++) {
            if ((mb >> i) & 1) {
                int q = i + is_hi*6;
                float f;
                if (pass < 6) {
                    int l = pass >> 1, kind = pass & 1;   // 0 = pre(lambda), 1 = post(phi)
                    f = resp[(l*12 + q)*3 + (kind ? 1 : 2)];
                } else {
                    f = headp[(pass - 6)*48 + q*2 + 1];
                }
                ph += f;
            }
        }
        float2 v = make_float2(cosf(ph), sinf(ph));
        int neg = 0;
        if (pass == 1 || pass == 5)       // CZ 0x555: in-half pairs
            neg = __popc(mb & (mb >> 1) & 0x15) & 1;
        else if (pass == 3)               // CZ 0x2AA: in-half pairs
            neg = __popc(mb & (mb >> 1) & 0x0A) & 1;
        if (neg) { v.x = -v.x; v.y = -v.y; }
        g_diag[pass*128 + m] = v;
    }
}

// ---------------- layouts ----------------
// A: amp d = (k<<8) | tid            (local = qubits 8..11 on k bits 0..3)
// B: amp d = (tid&31) | ((k&7)<<5) | ((tid>>5)<<8) | ((k>>3)<<11)
__device__ __forceinline__ int addrA(int tid, int k) { return (k<<8) | tid; }
__device__ __forceinline__ int addrB(int tid, int k) {
    return (tid & 31) | ((k & 7) << 5) | ((tid >> 5) << 8) | ((k >> 3) << 11);
}
__device__ __forceinline__ int ladd(int d) {   // CX-ladder gather source
    return ((d ^ (d << 1)) & 0xFFE) | (d & 1);
}

// ---------------- packed RY gate primitives (state stays u64) ----------------
__device__ __forceinline__ void ry_lane(u64 st[KREG], int tid, int i, float2 cs)
{
    unsigned lm = 1u << i;
    float s = ((tid >> i) & 1) ? cs.y : -cs.y;
    u64 c2 = pk2(cs.x, cs.x), s2 = pk2(s, s);
    #pragma unroll
    for (int k = 0; k < KREG; k++) {
        float2 v = up2(st[k]);
        float ox = __shfl_xor_sync(0xffffffffu, v.x, lm);
        float oy = __shfl_xor_sync(0xffffffffu, v.y, lm);
        st[k] = fma2_(c2, st[k], mul2_(s2, pk2(ox, oy)));
    }
}
__device__ __forceinline__ void ry_local(u64 st[KREG], int m, float2 cs)
{
    u64 c2 = pk2(cs.x, cs.x), s2 = pk2(cs.y, cs.y), ns2 = pk2(-cs.y, -cs.y);
    #pragma unroll
    for (int k = 0; k < KREG; k++) {
        if (k & m) continue;
        int kk = k | m;
        u64 a = st[k], b = st[kk];
        st[k]  = fma2_(c2, a, mul2_(ns2, b));
        st[kk] = fma2_(s2, a, mul2_(c2, b));
    }
}

// ---------------- diagonal passes (tables via L2) ----------------
__device__ __forceinline__ void diagA(u64 st[KREG], const float2* T, int tid)
{
    float2 L = __ldg(&T[tid & 63]);
    int tt = tid >> 6;
    #pragma unroll
    for (int k = 0; k < KREG; k++) {
        float2 u = cmul(L, __ldg(&T[64 + ((k<<2) | tt)]));
        float2 v = up2(st[k]);
        st[k] = pk2(v.x*u.x - v.y*u.y, v.x*u.y + v.y*u.x);
    }
}
__device__ __forceinline__ void diagB(u64 st[KREG], const float2* T, int tid)
{
    int lo0 = tid & 31, t57 = tid >> 5;
    #pragma unroll
    for (int k = 0; k < KREG; k++) {
        float2 L = __ldg(&T[lo0 | ((k & 1) << 5)]);
        float2 H = __ldg(&T[64 + (((k>>1) & 3) | (t57 << 2) | ((k>>3) << 5))]);
        float2 u = cmul(L, H);
        float2 v = up2(st[k]);
        st[k] = pk2(v.x*u.x - v.y*u.y, v.x*u.y + v.y*u.x);
    }
}

// ---------------- CX(0,11): local in both layouts ----------------
__device__ __forceinline__ void cx011(u64 st[KREG], int tid)
{
    if (tid & 1) {
        #pragma unroll
        for (int k = 0; k < 8; k++) {
            u64 t = st[k]; st[k] = st[k+8]; st[k+8] = t;
        }
    }
}

// ---------------- layout roundtrips ----------------
__device__ __forceinline__ void rtAB(u64 st[KREG], u64* work, int tid, bool ladder)
{
    __syncthreads();
    #pragma unroll
    for (int k = 0; k < KREG; k++) work[addrA(tid, k)] = st[k];
    __syncthreads();
    #pragma unroll
    for (int k = 0; k < KREG; k++) {
        int D = addrB(tid, k);
        st[k] = work[ladder ? ladd(D) : D];
    }
}
__device__ __forceinline__ void rtBA(u64 st[KREG], u64* work, int tid)
{
    __syncthreads();
    #pragma unroll
    for (int k = 0; k < KREG; k++) work[addrB(tid, k)] = st[k];
    __syncthreads();
    #pragma unroll
    for (int k = 0; k < KREG; k++) st[k] = work[addrA(tid, k)];
}

extern __shared__ u64 smem_u64[];
// [0,4096) work   [4096,8192) enc snapshot   then 180 float2 coeffs

__global__ void __launch_bounds__(NTHR, 3) qtf_main(const float* __restrict__ seq)
{
    u64* work   = smem_u64;
    u64* encs   = smem_u64 + 4096;
    float2* sry = (float2*)(smem_u64 + 8192);   // [0,36) res, [36,180) proj
    const int tid = threadIdx.x;
    const int bt  = blockIdx.x;
    const int t   = bt & (SEQ - 1);
    const float x = seq[bt];

    for (int j = tid; j < 36;  j += NTHR) sry[j]    = g_ryres[j];
    for (int j = tid; j < 144; j += NTHR) sry[36+j] = g_ryproj[j];

    u64 st[KREG];

    // ======== encode: product state with folded ladder+ring perm (layout A) ========
    {
        float2 F = make_float2(1.0f, 0.0f);
        float2 wv[6][2];   // qubits 0,1,8,9,10,11
        #pragma unroll
        for (int i = 0; i < NQ; i++) {
            float th = x * (float)(PI_D * (double)(i + 1) / 12.0);
            float ph = x * (float)(PI_D / (double)(i + 1));
            float s, c, sh, ch;
            __sincosf(0.5f*th, &s, &c);
            __sincosf(0.5f*ph, &sh, &ch);
            float am = (c - s) * 0.70710678118654752f;
            float ap = (c + s) * 0.70710678118654752f;
            float2 v0 = make_float2(am*ch, -am*sh);
            float2 v1 = make_float2(ap*ch,  ap*sh);
            if (i >= 2 && i <= 7) {
                int bit = ((tid >> (i-1)) ^ (tid >> i)) & 1;
                F = cmul(F, bit ? v1 : v0);
            } else {
                int vi = (i < 2) ? i : (i - 6);
                wv[vi][0] = v0; wv[vi][1] = v1;
            }
        }
        int a0 = tid & 1, a1 = (tid >> 1) & 1, a7 = (tid >> 7) & 1;
        #pragma unroll
        for (int k = 0; k < KREG; k++) {
            int k0 = k & 1, k1 = (k >> 1) & 1, k2 = (k >> 2) & 1, k3 = (k >> 3) & 1;
            float2 a = cmul(F, (a0 ^ k3)      ? wv[0][1] : wv[0][0]);
            a = cmul(a, (a0 ^ a1 ^ k3) ? wv[1][1] : wv[1][0]);
            a = cmul(a, (a7 ^ k0)      ? wv[2][1] : wv[2][0]);
            a = cmul(a, (k0 ^ k1)      ? wv[3][1] : wv[3][0]);
            a = cmul(a, (k1 ^ k2)      ? wv[4][1] : wv[4][0]);
            a = cmul(a, (k2 ^ k3)      ? wv[5][1] : wv[5][0]);
            st[k] = pk2(a.x, a.y);
        }
    }
    __syncthreads();   // coeff loads complete

    // ======== reservoir: diag(pre) / RY / diag(post+CZ) / CX ========
    // layer 0 (A -> B)
    diagA(st, g_diag + 0*128, tid);
    #pragma unroll
    for (int i = 0; i < 5; i++) ry_lane(st, tid, i, sry[i]);
    ry_local(st, 1, sry[8]);  ry_local(st, 2, sry[9]);
    ry_local(st, 4, sry[10]); ry_local(st, 8, sry[11]);
    rtAB(st, work, tid, false);
    ry_local(st, 1, sry[5]);  ry_local(st, 2, sry[6]); ry_local(st, 4, sry[7]);
    diagB(st, g_diag + 1*128, tid);         // post0 + CZ(0x555) folded
    cx011(st, tid);
    // layer 1 (B -> A)
    diagB(st, g_diag + 2*128, tid);
    #pragma unroll
    for (int i = 0; i < 5; i++) ry_lane(st, tid, i, sry[12+i]);
    ry_local(st, 1, sry[12+5]); ry_local(st, 2, sry[12+6]);
    ry_local(st, 4, sry[12+7]); ry_local(st, 8, sry[12+11]);
    rtBA(st, work, tid);
    ry_local(st, 1, sry[12+8]); ry_local(st, 2, sry[12+9]); ry_local(st, 4, sry[12+10]);
    diagA(st, g_diag + 3*128, tid);         // post1 + CZ(0x2AA) separable part folded
    if (((tid >> 5) & (tid >> 6)) & 1) {    // CZ(0x2AA) straddle pair (5,6)
        #pragma unroll
        for (int k = 0; k < KREG; k++) st[k] ^= NEGM;
    }
    cx011(st, tid);
    // layer 2 (A -> B)
    diagA(st, g_diag + 4*128, tid);
    #pragma unroll
    for (int i = 0; i < 5; i++) ry_lane(st, tid, i, sry[24+i]);
    ry_local(st, 1, sry[24+8]);  ry_local(st, 2, sry[24+9]);
    ry_local(st, 4, sry[24+10]); ry_local(st, 8, sry[24+11]);
    rtAB(st, work, tid, false);
    ry_local(st, 1, sry[24+5]);  ry_local(st, 2, sry[24+6]); ry_local(st, 4, sry[24+7]);
    diagB(st, g_diag + 5*128, tid);         // post2 + CZ(0x555) folded
    cx011(st, tid);

    // snapshot encoded state (layout B; own cells only)
    #pragma unroll
    for (int k = 0; k < KREG; k++) encs[(k<<8) | tid] = st[k];

    // ======== projections (Q only at t = SEQ-1) ========
    __shared__ float red[NQ];
    const bool lastt = (t == SEQ - 1);
    bool first = true;
    for (int h = 0; h < 2; h++) {
        for (int p = 0; p < 3; p++) {
            if (p == 0 && !lastt) continue;
            if (!first) {
                #pragma unroll
                for (int k = 0; k < KREG; k++) st[k] = encs[(k<<8) | tid];
            }
            first = false;
            const int hp = h*3 + p;
            const float2* gp = sry + 36 + hp*24;
            // attn layer 0 (state in B)
            #pragma unroll
            for (int i = 0; i < 5; i++) ry_lane(st, tid, i, gp[i]);
            ry_local(st, 1, gp[5]); ry_local(st, 2, gp[6]);
            ry_local(st, 4, gp[7]); ry_local(st, 8, gp[11]);
            rtBA(st, work, tid);
            ry_local(st, 1, gp[8]); ry_local(st, 2, gp[9]); ry_local(st, 4, gp[10]);
            diagA(st, g_diag + (6 + hp)*128, tid);   // layer-0 RZ phases
            rtAB(st, work, tid, true);               // ladder folded into gather
            // attn layer 1 (state in B): final RZ diag dropped (|amp|^2)
            #pragma unroll
            for (int i = 0; i < 5; i++) ry_lane(st, tid, i, gp[12+i]);
            ry_local(st, 1, gp[12+5]); ry_local(st, 2, gp[12+6]);
            ry_local(st, 4, gp[12+7]); ry_local(st, 8, gp[12+11]);
            rtBA(st, work, tid);
            ry_local(st, 1, gp[12+8]); ry_local(st, 2, gp[12+9]); ry_local(st, 4, gp[12+10]);

            // ---- features (layout A, final ladder folded into sign masks) ----
            float S = 0.f, B0 = 0.f, B1 = 0.f, B2 = 0.f, B3 = 0.f;
            #pragma unroll
            for (int k = 0; k < KREG; k++) {
                float2 v = up2(st[k]);
                float pr = fmaf(v.x, v.x, v.y*v.y);
                S += pr;
                B0 += ( k          & 1) ? -pr : pr;
                B1 += ((k ^ (k>>1))& 1) ? -pr : pr;
                B2 += (__popc(k & 7)  & 1) ? -pr : pr;
                B3 += (__popc(k & 15) & 1) ? -pr : pr;
            }
            float tsgn = (__popc(tid) & 1) ? -1.f : 1.f;
            float acc[NQ];
            acc[0] = tsgn * B3;
            acc[1] = tsgn * B2;
            acc[2] = tsgn * B1;
            acc[3] = tsgn * B0;
            #pragma unroll
            for (int q = 4; q < NQ; q++) {
                int mt = 0xFF >> (q - 4);
                acc[q] = (__popc(tid & mt) & 1) ? -S : S;
            }
            #pragma unroll
            for (int q = 0; q < NQ; q++) {
                float v = acc[q];
                #pragma unroll
                for (int o = 16; o; o >>= 1)
                    v += __shfl_xor_sync(0xffffffffu, v, o);
                acc[q] = v;
            }
            if (tid < NQ) red[tid] = 0.f;
            __syncthreads();
            if ((tid & 31) == 0) {
                #pragma unroll
                for (int q = 0; q < NQ; q++) atomicAdd(&red[q], acc[q]);
            }
            __syncthreads();
            if (tid < NQ)
                g_qkv[(hp*BT + bt)*NQ + tid] = red[tid];
            __syncthreads();
        }
    }
}

// ---------------- attention (last row only) + MLP: one warp per head ----------------
__global__ void qtf_head(
    const float* __restrict__ W1, const float* __restrict__ b1,
    const float* __restrict__ W2, const float* __restrict__ b2,
    float* __restrict__ out)
{
    const int b   = blockIdx.x;
    const int tid = threadIdx.x;       // 64 threads: warp = head, lane covers s and s+32
    const int h   = tid >> 5;
    const int l   = tid & 31;
    __shared__ float feat[24];
    __shared__ float hdn[48];

    const float* Q = &g_qkv[((h*3 + 0)*BT + b*SEQ + (SEQ-1))*NQ];
    const float* K = &g_qkv[((h*3 + 1)*BT + b*SEQ)*NQ];
    const float* V = &g_qkv[((h*3 + 2)*BT + b*SEQ)*NQ];
    float sc0 = 0.f, sc1 = 0.f;
    #pragma unroll
    for (int q = 0; q < NQ; q++) {
        float qv = Q[q];
        sc0 = fmaf(qv, K[l*NQ + q],        sc0);
        sc1 = fmaf(qv, K[(l+32)*NQ + q],   sc1);
    }
    sc0 *= 0.28867513459481287f;   // 1/sqrt(12)
    sc1 *= 0.28867513459481287f;
    float m = fmaxf(sc0, sc1);
    #pragma unroll
    for (int o = 16; o; o >>= 1)
        m = fmaxf(m, __shfl_xor_sync(0xffffffffu, m, o));
    float e0 = expf(sc0 - m), e1 = expf(sc1 - m);
    float sum = e0 + e1;
    #pragma unroll
    for (int o = 16; o; o >>= 1)
        sum += __shfl_xor_sync(0xffffffffu, sum, o);
    float inv = 1.0f / sum;
    float w0 = e0 * inv, w1 = e1 * inv;
    #pragma unroll
    for (int d = 0; d < NQ; d++) {
        float v = fmaf(w0, V[l*NQ + d], w1 * V[(l+32)*NQ + d]);
        #pragma unroll
        for (int o = 16; o; o >>= 1)
            v += __shfl_xor_sync(0xffffffffu, v, o);
        if (l == 0) feat[h*NQ + d] = v;
    }
    __syncthreads();

    if (tid < 48) {
        float a = b1[tid];
        #pragma unroll
        for (int i = 0; i < 24; i++) a = fmaf(feat[i], W1[i*48 + tid], a);
        hdn[tid] = 0.5f * a * (1.0f + erff(a * 0.7071067811865476f));
    }
    __syncthreads();
    if (tid < 4) {
        float a = b2[tid];
        #pragma unroll
        for (int j = 0; j < 48; j++) a = fmaf(hdn[j], W2[j*4 + tid], a);
        out[b*4 + tid] = a;
    }
}

extern "C" void kernel_launch(void* const* d_in, const int* in_sizes, int n_in,
                              void* d_out, int out_size)
{
    const float* seq   = (const float*)d_in[0];
    const float* resp  = (const float*)d_in[1];
    const float* headp = (const float*)d_in[2];
    const float* W1    = (const float*)d_in[3];
    const float* b1    = (const float*)d_in[4];
    const float* W2    = (const float*)d_in[5];
    const float* b2    = (const float*)d_in[6];
    float* out = (float*)d_out;

    size_t shbytes = 8192ull*sizeof(u64) + 180ull*sizeof(float2);   // 66,976 B -> occ 3
    cudaFuncSetAttribute(qtf_main, cudaFuncAttributeMaxDynamicSharedMemorySize, (int)shbytes);

    qtf_setup<<<8, 256>>>(resp, headp);
    qtf_main<<<BT, NTHR, shbytes>>>(seq);
    qtf_head<<<BATCH, 64>>>(W1, b1, W2, b2, out);
}

// round 11
// speedup vs baseline: 1.7517x; 1.0439x over previous
#include <cuda_runtime.h>
#include <math.h>

#define NQ    12
#define DIM   4096
#define BATCH 8
#define SEQ   64
#define BT    (BATCH*SEQ)
#define NTHR  256
#define KREG  16

#define PI_D 3.14159265358979323846

typedef unsigned long long u64;

// QKV features [head*3+proj][bt][12]
__device__ float  g_qkv[6*BT*NQ];
__device__ float2 g_ryres[36];        // reservoir RY coeffs (cos(t/2), sin(t/2))
__device__ float2 g_ryproj[144];      // projection RY coeffs
__device__ float2 g_diag[12*128];     // diag tables: pass*128 + (lo:0-63 | hi:64-127)
__device__ int    g_done;             // completion counter (reset by last CTA)

// ---------------- packed f32x2 helpers ----------------
__device__ __forceinline__ u64 pk2(float lo, float hi) {
    u64 r; asm("mov.b64 %0,{%1,%2};" : "=l"(r) : "f"(lo), "f"(hi)); return r;
}
__device__ __forceinline__ float2 up2(u64 v) {
    float2 r; asm("mov.b64 {%0,%1},%2;" : "=f"(r.x), "=f"(r.y) : "l"(v)); return r;
}
__device__ __forceinline__ u64 mul2_(u64 a, u64 b) {
    u64 d; asm("mul.rn.f32x2 %0,%1,%2;" : "=l"(d) : "l"(a), "l"(b)); return d;
}
__device__ __forceinline__ u64 fma2_(u64 a, u64 b, u64 c) {
    u64 d; asm("fma.rn.f32x2 %0,%1,%2,%3;" : "=l"(d) : "l"(a), "l"(b), "l"(c)); return d;
}
#define NEGM 0x8000000080000000ULL

// ---------------- complex helpers ----------------
__device__ __forceinline__ float2 cmul(float2 a, float2 b) {
    return make_float2(a.x*b.x - a.y*b.y, a.x*b.y + a.y*b.x);
}

// ---------------- setup: RY coeffs + diag tables (CZ folded in) ----------------
__global__ void qtf_setup(const float* __restrict__ resp, const float* __restrict__ headp)
{
    int j = blockIdx.x * blockDim.x + threadIdx.x;
    if (j < 36) {
        float t = resp[j*3];
        g_ryres[j] = make_float2(cosf(0.5f*t), sinf(0.5f*t));
    } else if (j < 180) {
        int s = j - 36, hp = s / 24, gi = s % 24;
        float t = headp[hp*48 + gi*2];
        g_ryproj[s] = make_float2(cosf(0.5f*t), sinf(0.5f*t));
    }
    int e = j - 192;
    if (e >= 0 && e < 12*128) {
        int pass = e >> 7, m = e & 127;
        int is_hi = (m >> 6) & 1, mb = m & 63;
        float ph = 0.f;
        for (int i = 0; i < 6; i++) {
            if ((mb >> i) & 1) {
                int q = i + is_hi*6;
                float f;
                if (pass < 6) {
                    int l = pass >> 1, kind = pass & 1;
                    f = resp[(l*12 + q)*3 + (kind ? 1 : 2)];
                } else {
                    f = headp[(pass - 6)*48 + q*2 + 1];
                }
                ph += f;
            }
        }
        float2 v = make_float2(cosf(ph), sinf(ph));
        int neg = 0;
        if (pass == 1 || pass == 5)       // CZ 0x555 in-half pairs
            neg = __popc(mb & (mb >> 1) & 0x15) & 1;
        else if (pass == 3)               // CZ 0x2AA in-half pairs
            neg = __popc(mb & (mb >> 1) & 0x0A) & 1;
        if (neg) { v.x = -v.x; v.y = -v.y; }
        g_diag[pass*128 + m] = v;
    }
}

// ---------------- layouts ----------------
__device__ __forceinline__ int addrA(int tid, int k) { return (k<<8) | tid; }
__device__ __forceinline__ int addrB(int tid, int k) {
    return (tid & 31) | ((k & 7) << 5) | ((tid >> 5) << 8) | ((k >> 3) << 11);
}
__device__ __forceinline__ int ladd(int d) {
    return ((d ^ (d << 1)) & 0xFFE) | (d & 1);
}

// ---------------- packed RY gate primitives ----------------
__device__ __forceinline__ void ry_lane(u64 st[KREG], int tid, int i, float2 cs)
{
    unsigned lm = 1u << i;
    float s = ((tid >> i) & 1) ? cs.y : -cs.y;
    u64 c2 = pk2(cs.x, cs.x), s2 = pk2(s, s);
    #pragma unroll
    for (int k = 0; k < KREG; k++) {
        float2 v = up2(st[k]);
        float ox = __shfl_xor_sync(0xffffffffu, v.x, lm);
        float oy = __shfl_xor_sync(0xffffffffu, v.y, lm);
        st[k] = fma2_(c2, st[k], mul2_(s2, pk2(ox, oy)));
    }
}
__device__ __forceinline__ void ry_local(u64 st[KREG], int m, float2 cs)
{
    u64 c2 = pk2(cs.x, cs.x), s2 = pk2(cs.y, cs.y), ns2 = pk2(-cs.y, -cs.y);
    #pragma unroll
    for (int k = 0; k < KREG; k++) {
        if (k & m) continue;
        int kk = k | m;
        u64 a = st[k], b = st[kk];
        st[k]  = fma2_(c2, a, mul2_(ns2, b));
        st[kk] = fma2_(s2, a, mul2_(c2, b));
    }
}

// ---------------- diagonal passes ----------------
__device__ __forceinline__ void diagA(u64 st[KREG], const float2* T, int tid)
{
    float2 L = __ldg(&T[tid & 63]);
    int tt = tid >> 6;
    #pragma unroll
    for (int k = 0; k < KREG; k++) {
        float2 u = cmul(L, __ldg(&T[64 + ((k<<2) | tt)]));
        float2 v = up2(st[k]);
        st[k] = pk2(v.x*u.x - v.y*u.y, v.x*u.y + v.y*u.x);
    }
}
__device__ __forceinline__ void diagB(u64 st[KREG], const float2* T, int tid)
{
    int lo0 = tid & 31, t57 = tid >> 5;
    #pragma unroll
    for (int k = 0; k < KREG; k++) {
        float2 L = __ldg(&T[lo0 | ((k & 1) << 5)]);
        float2 H = __ldg(&T[64 + (((k>>1) & 3) | (t57 << 2) | ((k>>3) << 5))]);
        float2 u = cmul(L, H);
        float2 v = up2(st[k]);
        st[k] = pk2(v.x*u.x - v.y*u.y, v.x*u.y + v.y*u.x);
    }
}

__device__ __forceinline__ void cx011(u64 st[KREG], int tid)
{
    if (tid & 1) {
        #pragma unroll
        for (int k = 0; k < 8; k++) {
            u64 t = st[k]; st[k] = st[k+8]; st[k+8] = t;
        }
    }
}

// ---------------- layout roundtrips ----------------
__device__ __forceinline__ void rtAB(u64 st[KREG], u64* work, int tid, bool ladder)
{
    __syncthreads();
    #pragma unroll
    for (int k = 0; k < KREG; k++) work[addrA(tid, k)] = st[k];
    __syncthreads();
    #pragma unroll
    for (int k = 0; k < KREG; k++) {
        int D = addrB(tid, k);
        st[k] = work[ladder ? ladd(D) : D];
    }
}
__device__ __forceinline__ void rtBA(u64 st[KREG], u64* work, int tid)
{
    __syncthreads();
    #pragma unroll
    for (int k = 0; k < KREG; k++) work[addrB(tid, k)] = st[k];
    __syncthreads();
    #pragma unroll
    for (int k = 0; k < KREG; k++) st[k] = work[addrA(tid, k)];
}

extern __shared__ u64 smem_u64[];
// [0,4096) work   [4096,8192) enc snapshot   then 180 float2 coeffs

__global__ void __launch_bounds__(NTHR, 3) qtf_main(
    const float* __restrict__ seq,
    const float* __restrict__ W1, const float* __restrict__ b1,
    const float* __restrict__ W2, const float* __restrict__ b2,
    float* __restrict__ out)
{
    u64* work   = smem_u64;
    u64* encs   = smem_u64 + 4096;
    float2* sry = (float2*)(smem_u64 + 8192);
    const int tid = threadIdx.x;
    // heavy-first remap: blocks 0..7 are the t=63 (6-projection) CTAs
    int b_, t_;
    if (blockIdx.x < 8) { b_ = blockIdx.x; t_ = SEQ - 1; }
    else { int ix = blockIdx.x - 8; b_ = ix / 63; t_ = ix % 63; }
    const int bt = b_ * SEQ + t_;
    const int t  = t_;
    const float x = seq[bt];

    for (int j = tid; j < 36;  j += NTHR) sry[j]    = g_ryres[j];
    for (int j = tid; j < 144; j += NTHR) sry[36+j] = g_ryproj[j];

    u64 st[KREG];

    // ======== encode: product state with folded ladder+ring perm (layout A) ========
    {
        float2 F = make_float2(1.0f, 0.0f);
        float2 wv[6][2];
        #pragma unroll
        for (int i = 0; i < NQ; i++) {
            float th = x * (float)(PI_D * (double)(i + 1) / 12.0);
            float ph = x * (float)(PI_D / (double)(i + 1));
            float s, c, sh, ch;
            __sincosf(0.5f*th, &s, &c);
            __sincosf(0.5f*ph, &sh, &ch);
            float am = (c - s) * 0.70710678118654752f;
            float ap = (c + s) * 0.70710678118654752f;
            float2 v0 = make_float2(am*ch, -am*sh);
            float2 v1 = make_float2(ap*ch,  ap*sh);
            if (i >= 2 && i <= 7) {
                int bit = ((tid >> (i-1)) ^ (tid >> i)) & 1;
                F = cmul(F, bit ? v1 : v0);
            } else {
                int vi = (i < 2) ? i : (i - 6);
                wv[vi][0] = v0; wv[vi][1] = v1;
            }
        }
        int a0 = tid & 1, a1 = (tid >> 1) & 1, a7 = (tid >> 7) & 1;
        #pragma unroll
        for (int k = 0; k < KREG; k++) {
            int k0 = k & 1, k1 = (k >> 1) & 1, k2 = (k >> 2) & 1, k3 = (k >> 3) & 1;
            float2 a = cmul(F, (a0 ^ k3)      ? wv[0][1] : wv[0][0]);
            a = cmul(a, (a0 ^ a1 ^ k3) ? wv[1][1] : wv[1][0]);
            a = cmul(a, (a7 ^ k0)      ? wv[2][1] : wv[2][0]);
            a = cmul(a, (k0 ^ k1)      ? wv[3][1] : wv[3][0]);
            a = cmul(a, (k1 ^ k2)      ? wv[4][1] : wv[4][0]);
            a = cmul(a, (k2 ^ k3)      ? wv[5][1] : wv[5][0]);
            st[k] = pk2(a.x, a.y);
        }
    }
    __syncthreads();

    // ======== reservoir ========
    diagA(st, g_diag + 0*128, tid);
    #pragma unroll
    for (int i = 0; i < 5; i++) ry_lane(st, tid, i, sry[i]);
    ry_local(st, 1, sry[8]);  ry_local(st, 2, sry[9]);
    ry_local(st, 4, sry[10]); ry_local(st, 8, sry[11]);
    rtAB(st, work, tid, false);
    ry_local(st, 1, sry[5]);  ry_local(st, 2, sry[6]); ry_local(st, 4, sry[7]);
    diagB(st, g_diag + 1*128, tid);
    cx011(st, tid);

    diagB(st, g_diag + 2*128, tid);
    #pragma unroll
    for (int i = 0; i < 5; i++) ry_lane(st, tid, i, sry[12+i]);
    ry_local(st, 1, sry[12+5]); ry_local(st, 2, sry[12+6]);
    ry_local(st, 4, sry[12+7]); ry_local(st, 8, sry[12+11]);
    rtBA(st, work, tid);
    ry_local(st, 1, sry[12+8]); ry_local(st, 2, sry[12+9]); ry_local(st, 4, sry[12+10]);
    diagA(st, g_diag + 3*128, tid);
    if (((tid >> 5) & (tid >> 6)) & 1) {
        #pragma unroll
        for (int k = 0; k < KREG; k++) st[k] ^= NEGM;
    }
    cx011(st, tid);

    diagA(st, g_diag + 4*128, tid);
    #pragma unroll
    for (int i = 0; i < 5; i++) ry_lane(st, tid, i, sry[24+i]);
    ry_local(st, 1, sry[24+8]);  ry_local(st, 2, sry[24+9]);
    ry_local(st, 4, sry[24+10]); ry_local(st, 8, sry[24+11]);
    rtAB(st, work, tid, false);
    ry_local(st, 1, sry[24+5]);  ry_local(st, 2, sry[24+6]); ry_local(st, 4, sry[24+7]);
    diagB(st, g_diag + 5*128, tid);
    cx011(st, tid);

    #pragma unroll
    for (int k = 0; k < KREG; k++) encs[(k<<8) | tid] = st[k];

    // ======== projections (Q only at t = SEQ-1) ========
    __shared__ float red[NQ];
    const bool lastt = (t == SEQ - 1);
    bool first = true;
    for (int h = 0; h < 2; h++) {
        for (int p = 0; p < 3; p++) {
            if (p == 0 && !lastt) continue;
            if (!first) {
                #pragma unroll
                for (int k = 0; k < KREG; k++) st[k] = encs[(k<<8) | tid];
            }
            first = false;
            const int hp = h*3 + p;
            const float2* gp = sry + 36 + hp*24;
            #pragma unroll
            for (int i = 0; i < 5; i++) ry_lane(st, tid, i, gp[i]);
            ry_local(st, 1, gp[5]); ry_local(st, 2, gp[6]);
            ry_local(st, 4, gp[7]); ry_local(st, 8, gp[11]);
            rtBA(st, work, tid);
            ry_local(st, 1, gp[8]); ry_local(st, 2, gp[9]); ry_local(st, 4, gp[10]);
            diagA(st, g_diag + (6 + hp)*128, tid);
            rtAB(st, work, tid, true);
            #pragma unroll
            for (int i = 0; i < 5; i++) ry_lane(st, tid, i, gp[12+i]);
            ry_local(st, 1, gp[12+5]); ry_local(st, 2, gp[12+6]);
            ry_local(st, 4, gp[12+7]); ry_local(st, 8, gp[12+11]);
            rtBA(st, work, tid);
            ry_local(st, 1, gp[12+8]); ry_local(st, 2, gp[12+9]); ry_local(st, 4, gp[12+10]);

            float S = 0.f, B0 = 0.f, B1 = 0.f, B2 = 0.f, B3 = 0.f;
            #pragma unroll
            for (int k = 0; k < KREG; k++) {
                float2 v = up2(st[k]);
                float pr = fmaf(v.x, v.x, v.y*v.y);
                S += pr;
                B0 += ( k          & 1) ? -pr : pr;
                B1 += ((k ^ (k>>1))& 1) ? -pr : pr;
                B2 += (__popc(k & 7)  & 1) ? -pr : pr;
                B3 += (__popc(k & 15) & 1) ? -pr : pr;
            }
            float tsgn = (__popc(tid) & 1) ? -1.f : 1.f;
            float acc[NQ];
            acc[0] = tsgn * B3;
            acc[1] = tsgn * B2;
            acc[2] = tsgn * B1;
            acc[3] = tsgn * B0;
            #pragma unroll
            for (int q = 4; q < NQ; q++) {
                int mt = 0xFF >> (q - 4);
                acc[q] = (__popc(tid & mt) & 1) ? -S : S;
            }
            #pragma unroll
            for (int q = 0; q < NQ; q++) {
                float v = acc[q];
                #pragma unroll
                for (int o = 16; o; o >>= 1)
                    v += __shfl_xor_sync(0xffffffffu, v, o);
                acc[q] = v;
            }
            if (tid < NQ) red[tid] = 0.f;
            __syncthreads();
            if ((tid & 31) == 0) {
                #pragma unroll
                for (int q = 0; q < NQ; q++) atomicAdd(&red[q], acc[q]);
            }
            __syncthreads();
            if (tid < NQ)
                g_qkv[(hp*BT + bt)*NQ + tid] = red[tid];
            __syncthreads();
        }
    }

    // ======== last CTA runs attention + MLP inline ========
    __shared__ int s_last;
    __threadfence();
    if (tid == 0) s_last = (atomicAdd(&g_done, 1) == BT - 1) ? 1 : 0;
    __syncthreads();
    if (!s_last) return;
    if (tid == 0) g_done = 0;        // reset for next graph replay
    __threadfence();

    float* feat = (float*)work;      // 8 b * 24
    float* hdn  = feat + 192;        // 8 b * 48
    const int w = tid >> 5, l = tid & 31;
    for (int task = w; task < 16; task += 8) {
        int b = task >> 1, h = task & 1;
        const float* Q = &g_qkv[((h*3 + 0)*BT + b*SEQ + (SEQ-1))*NQ];
        const float* K = &g_qkv[((h*3 + 1)*BT + b*SEQ)*NQ];
        const float* V = &g_qkv[((h*3 + 2)*BT + b*SEQ)*NQ];
        float sc0 = 0.f, sc1 = 0.f;
        #pragma unroll
        for (int q = 0; q < NQ; q++) {
            float qv = Q[q];
            sc0 = fmaf(qv, K[l*NQ + q],      sc0);
            sc1 = fmaf(qv, K[(l+32)*NQ + q], sc1);
        }
        sc0 *= 0.28867513459481287f;
        sc1 *= 0.28867513459481287f;
        float m = fmaxf(sc0, sc1);
        #pragma unroll
        for (int o = 16; o; o >>= 1)
            m = fmaxf(m, __shfl_xor_sync(0xffffffffu, m, o));
        float e0 = expf(sc0 - m), e1 = expf(sc1 - m);
        float sum = e0 + e1;
        #pragma unroll
        for (int o = 16; o; o >>= 1)
            sum += __shfl_xor_sync(0xffffffffu, sum, o);
        float inv = 1.0f / sum;
        float w0 = e0 * inv, w1 = e1 * inv;
        #pragma unroll
        for (int d = 0; d < NQ; d++) {
            float v = fmaf(w0, V[l*NQ + d], w1 * V[(l+32)*NQ + d]);
            #pragma unroll
            for (int o = 16; o; o >>= 1)
                v += __shfl_xor_sync(0xffffffffu, v, o);
            if (l == 0) feat[b*24 + h*NQ + d] = v;
        }
    }
    __syncthreads();
    for (int idx = tid; idx < 384; idx += NTHR) {
        int b = idx / 48, j = idx % 48;
        float a = b1[j];
        #pragma unroll
        for (int i = 0; i < 24; i++) a = fmaf(feat[b*24 + i], W1[i*48 + j], a);
        hdn[b*48 + j] = 0.5f * a * (1.0f + erff(a * 0.7071067811865476f));
    }
    __syncthreads();
    if (tid < 32) {
        int b = tid >> 2, o = tid & 3;
        float a = b2[o];
        #pragma unroll
        for (int j = 0; j < 48; j++) a = fmaf(hdn[b*48 + j], W2[j*4 + o], a);
        out[b*4 + o] = a;
    }
}

extern "C" void kernel_launch(void* const* d_in, const int* in_sizes, int n_in,
                              void* d_out, int out_size)
{
    const float* seq   = (const float*)d_in[0];
    const float* resp  = (const float*)d_in[1];
    const float* headp = (const float*)d_in[2];
    const float* W1    = (const float*)d_in[3];
    const float* b1    = (const float*)d_in[4];
    const float* W2    = (const float*)d_in[5];
    const float* b2    = (const float*)d_in[6];
    float* out = (float*)d_out;

    size_t shbytes = 8192ull*sizeof(u64) + 180ull*sizeof(float2);   // 66,976 B -> occ 3
    cudaFuncSetAttribute(qtf_main, cudaFuncAttributeMaxDynamicSharedMemorySize, (int)shbytes);

    qtf_setup<<<8, 256>>>(resp, headp);
    qtf_main<<<BT, NTHR, shbytes>>>(seq, W1, b1, W2, b2, out);
}